// round 8
// baseline (speedup 1.0000x reference)
#include <cuda_runtime.h>
#include <cuda_fp16.h>
#include <math.h>

// Problem constants (fixed by the dataset)
#define NFEAT 128
#define F1    256      // H1*NHID
#define H1    4
#define NHID  64
#define NCLS  16
#define MAXN  50048
#define MAXE  800000

#define NEG_SLOPE 0.2f

// ---------------- scratch (static __device__, no allocation) ----------------
__device__ __align__(16) __half g_obsh[MAXN * NFEAT];  // obs fp16 (tail rows stay 0)
__device__ __align__(16) __half g_w1h [NFEAT * F1];    // W1 fp16
__device__ __align__(16) __half g_xw1h[MAXN * F1];     // layer1 x@W1 (fp16)
__device__ __align__(16) __half g_x2h [MAXN * F1];     // layer1 output after ELU (fp16)
__device__ __align__(16) float g_a1s[MAXN * H1];
__device__ __align__(16) float g_a1d[MAXN * H1];
__device__ __align__(16) float g_xw2[MAXN * NCLS];
__device__ float g_a2s[MAXN];
__device__ float g_a2d[MAXN];
__device__ int   g_cnt[MAXN];
__device__ int   g_off[MAXN];
__device__ int   g_cur[MAXN];
__device__ int   g_srcs[MAXE];                 // src node id, bucketed by dst
__device__ int   g_epos[MAXE];                 // edge i -> CSR slot
__device__ __align__(8) uint2 g_w1e[MAXE];     // layer1 edge weights, fp16 x4 heads
__device__ float g_w2e[MAXE];                  // layer2 edge weights
__device__ int   g_is64;                       // 1 if edge_index delivered as int64

__device__ __forceinline__ float leaky(float x) {
    return x > 0.f ? x : NEG_SLOPE * x;
}

__device__ __forceinline__ int load_idx(const void* p, int e, int part, int i) {
    if (g_is64) {
        return (int)((const long long*)p)[(long long)part * e + i];
    } else {
        return ((const int*)p)[(long long)part * e + i];
    }
}

// ---------------- prep: conversions + zeroing + dtype probe ----------------
__global__ void prep_kernel(const float* __restrict__ obs,
                            const float* __restrict__ W1,
                            const void* ei, int e, int n, int m4) {
    int i = blockIdx.x * blockDim.x + threadIdx.x;
    if (i < m4) {                       // obs fp32 -> fp16 (float4 granularity)
        float4 v = *(const float4*)&obs[i * 4];
        __half2* dst = (__half2*)&g_obsh[i * 4];
        dst[0] = __floats2half2_rn(v.x, v.y);
        dst[1] = __floats2half2_rn(v.z, v.w);
    }
    if (i < NFEAT * F1 / 4) {           // W1 fp32 -> fp16
        float4 v = *(const float4*)&W1[i * 4];
        __half2* dst = (__half2*)&g_w1h[i * 4];
        dst[0] = __floats2half2_rn(v.x, v.y);
        dst[1] = __floats2half2_rn(v.z, v.w);
    }
    if (i < n) g_cnt[i] = 0;
    if (i == 0) {
        // dtype probe: first 32 slots as int64; all-in-range => int64
        const long long* p = (const long long*)ei;
        int ok64 = 1;
        int cnt = e < 32 ? e : 32;
        for (int k = 0; k < cnt; k++) {
            long long v = p[k];
            if (v < 0 || v >= (long long)n) { ok64 = 0; break; }
        }
        g_is64 = ok64;
    }
}

// ---------------- hist: degree histogram ----------------
__global__ void hist_kernel(const void* __restrict__ ei, int e, int n) {
    int i = blockIdx.x * blockDim.x + threadIdx.x;
    if (i < e) {
        int d = load_idx(ei, e, 1, i);
        if (d >= 0 && d < n) atomicAdd(&g_cnt[d], 1);
    }
}

// ---------------- single-block exclusive scan ----------------
#define SC_T 1024
__global__ void __launch_bounds__(SC_T) scan_kernel(int n) {
    __shared__ int warp_sums[32];
    int t = threadIdx.x;
    int C = (n + SC_T - 1) / SC_T;
    int base = t * C;
    int sum = 0;
    for (int k = 0; k < C; k++) {
        int idx = base + k;
        if (idx < n) sum += g_cnt[idx];
    }
    int lane = t & 31, wid = t >> 5;
    int v = sum;
#pragma unroll
    for (int off = 1; off < 32; off <<= 1) {
        int u = __shfl_up_sync(0xffffffffu, v, off);
        if (lane >= off) v += u;
    }
    if (lane == 31) warp_sums[wid] = v;
    __syncthreads();
    if (wid == 0) {
        int w = warp_sums[lane];
#pragma unroll
        for (int off = 1; off < 32; off <<= 1) {
            int u = __shfl_up_sync(0xffffffffu, w, off);
            if (lane >= off) w += u;
        }
        warp_sums[lane] = w;
    }
    __syncthreads();
    int run = v - sum + (wid > 0 ? warp_sums[wid - 1] : 0);   // exclusive prefix
    for (int k = 0; k < C; k++) {
        int idx = base + k;
        if (idx < n) {
            int c = g_cnt[idx];
            g_off[idx] = run;
            g_cur[idx] = run;
            run += c;
        }
    }
}

// ---------------- GEMM1 (HMMA) + fused att1 ----------------
#define G1_PAD 72
__global__ void __launch_bounds__(256, 2) gemm1_mma_kernel(
        const float* __restrict__ att_s, const float* __restrict__ att_d, int M) {
    __shared__ __half As [128][G1_PAD];
    __shared__ __half Bst[128][G1_PAD];
    __shared__ float ps_s[128][4];
    __shared__ float pd_s[128][4];
    const int tid  = threadIdx.x;
    const int wid  = tid >> 5;
    const int lane = tid & 31;
    const int wm = wid >> 2;
    const int wn = wid & 3;
    const int g  = lane >> 2;
    const int t  = lane & 3;
    const int row0 = blockIdx.y * 128;
    const int col0 = blockIdx.x * 128;

    float c[4][4][4];
#pragma unroll
    for (int mt = 0; mt < 4; mt++)
#pragma unroll
        for (int nt = 0; nt < 4; nt++)
#pragma unroll
            for (int q = 0; q < 4; q++) c[mt][nt][q] = 0.f;

    for (int kb = 0; kb < NFEAT; kb += 64) {
#pragma unroll
        for (int i = 0; i < 8; i++) {
            int idx = tid + i * 256;
            int r = idx >> 4;
            int q = idx & 15;
            *(uint2*)&As[r][q * 4] =
                *(const uint2*)&g_obsh[(row0 + r) * NFEAT + kb + q * 4];
        }
#pragma unroll
        for (int i = 0; i < 8; i++) {
            int idx = tid + i * 256;
            int kr = idx >> 5;
            int nq = idx & 31;
            uint2 v = *(const uint2*)&g_w1h[(kb + kr) * F1 + col0 + nq * 4];
            const __half* hv = (const __half*)&v;
            int nb = nq * 4;
            Bst[nb + 0][kr] = hv[0];
            Bst[nb + 1][kr] = hv[1];
            Bst[nb + 2][kr] = hv[2];
            Bst[nb + 3][kr] = hv[3];
        }
        __syncthreads();
#pragma unroll
        for (int ks = 0; ks < 64; ks += 16) {
            unsigned a[4][4];
#pragma unroll
            for (int mt = 0; mt < 4; mt++) {
                int mr = wm * 64 + mt * 16;
                a[mt][0] = *(const unsigned*)&As[mr + g    ][ks + t * 2    ];
                a[mt][1] = *(const unsigned*)&As[mr + g + 8][ks + t * 2    ];
                a[mt][2] = *(const unsigned*)&As[mr + g    ][ks + t * 2 + 8];
                a[mt][3] = *(const unsigned*)&As[mr + g + 8][ks + t * 2 + 8];
            }
            unsigned b[4][2];
#pragma unroll
            for (int nt = 0; nt < 4; nt++) {
                int nc = wn * 32 + nt * 8;
                b[nt][0] = *(const unsigned*)&Bst[nc + g][ks + t * 2    ];
                b[nt][1] = *(const unsigned*)&Bst[nc + g][ks + t * 2 + 8];
            }
#pragma unroll
            for (int mt = 0; mt < 4; mt++)
#pragma unroll
                for (int nt = 0; nt < 4; nt++) {
                    asm volatile(
                        "mma.sync.aligned.m16n8k16.row.col.f32.f16.f16.f32 "
                        "{%0,%1,%2,%3}, {%4,%5,%6,%7}, {%8,%9}, {%0,%1,%2,%3};\n"
                        : "+f"(c[mt][nt][0]), "+f"(c[mt][nt][1]),
                          "+f"(c[mt][nt][2]), "+f"(c[mt][nt][3])
                        : "r"(a[mt][0]), "r"(a[mt][1]), "r"(a[mt][2]), "r"(a[mt][3]),
                          "r"(b[nt][0]), "r"(b[nt][1]));
                }
        }
        __syncthreads();
    }

    float psr[8], pdr[8];
#pragma unroll
    for (int ri = 0; ri < 8; ri++) { psr[ri] = 0.f; pdr[ri] = 0.f; }

#pragma unroll
    for (int mt = 0; mt < 4; mt++) {
#pragma unroll
        for (int nt = 0; nt < 4; nt++) {
            int colg = col0 + wn * 32 + nt * 8 + t * 2;
            float a_s0 = att_s[colg], a_s1 = att_s[colg + 1];
            float a_d0 = att_d[colg], a_d1 = att_d[colg + 1];
            psr[mt*2+0] += c[mt][nt][0] * a_s0 + c[mt][nt][1] * a_s1;
            pdr[mt*2+0] += c[mt][nt][0] * a_d0 + c[mt][nt][1] * a_d1;
            psr[mt*2+1] += c[mt][nt][2] * a_s0 + c[mt][nt][3] * a_s1;
            pdr[mt*2+1] += c[mt][nt][2] * a_d0 + c[mt][nt][3] * a_d1;

            int row = row0 + wm * 64 + mt * 16 + g;
            if (row < M)
                *(__half2*)&g_xw1h[row * F1 + colg] =
                    __floats2half2_rn(c[mt][nt][0], c[mt][nt][1]);
            if (row + 8 < M)
                *(__half2*)&g_xw1h[(row + 8) * F1 + colg] =
                    __floats2half2_rn(c[mt][nt][2], c[mt][nt][3]);
        }
    }
#pragma unroll
    for (int ri = 0; ri < 8; ri++) {
        psr[ri] += __shfl_xor_sync(0xffffffffu, psr[ri], 1);
        psr[ri] += __shfl_xor_sync(0xffffffffu, psr[ri], 2);
        pdr[ri] += __shfl_xor_sync(0xffffffffu, pdr[ri], 1);
        pdr[ri] += __shfl_xor_sync(0xffffffffu, pdr[ri], 2);
    }
    if (t == 0) {
#pragma unroll
        for (int ri = 0; ri < 8; ri++) {
            int row = wm * 64 + (ri >> 1) * 16 + g + (ri & 1) * 8;
            ps_s[row][wn] = psr[ri];
            pd_s[row][wn] = pdr[ri];
        }
    }
    __syncthreads();
    if (tid < 128) {
        int node = row0 + tid;
        if (node < M) {
            int hb = blockIdx.x * 2;
            g_a1s[node * H1 + hb    ] = ps_s[tid][0] + ps_s[tid][1];
            g_a1s[node * H1 + hb + 1] = ps_s[tid][2] + ps_s[tid][3];
            g_a1d[node * H1 + hb    ] = pd_s[tid][0] + pd_s[tid][1];
            g_a1d[node * H1 + hb + 1] = pd_s[tid][2] + pd_s[tid][3];
        }
    }
}

// ---------------- scatter: bucket srcs by dst + layer1 edge weights ----------------
__global__ void scatter_kernel(const void* __restrict__ ei, int e, int n) {
    int i = blockIdx.x * blockDim.x + threadIdx.x;
    if (i < e) {
        int d = load_idx(ei, e, 1, i);
        int s = load_idx(ei, e, 0, i);
        if (d >= 0 && d < n && s >= 0 && s < n) {
            int p = atomicAdd(&g_cur[d], 1);
            if (p >= 0 && p < MAXE) {
                g_srcs[p] = s;
                g_epos[i] = p;
                float4 as = *(const float4*)&g_a1s[s * H1];
                float4 ad = *(const float4*)&g_a1d[d * H1];
                float w0 = __expf(leaky(as.x + ad.x));
                float w1 = __expf(leaky(as.y + ad.y));
                float w2 = __expf(leaky(as.z + ad.z));
                float w3 = __expf(leaky(as.w + ad.w));
                __half2 h0 = __floats2half2_rn(w0, w1);
                __half2 h1 = __floats2half2_rn(w2, w3);
                uint2 packed;
                packed.x = *(unsigned*)&h0;
                packed.y = *(unsigned*)&h1;
                g_w1e[p] = packed;
            }
        }
    }
}

// ---------------- agg1: 2 warps/node; weights precomputed; bias + ELU ----------------
__global__ void agg1_kernel(const float* __restrict__ bias1, int n) {
    int w2 = (blockIdx.x * blockDim.x + threadIdx.x) >> 5;
    int node = w2 >> 1;
    int hs   = w2 & 1;                 // which half of the 256 features
    int lane = threadIdx.x & 31;
    if (node >= n) return;

    int fb = hs * 128 + lane * 4;      // 4 contiguous halves per lane
    int head = fb >> 6;
    float adh = g_a1d[node * H1 + head];
    float ash = g_a1s[node * H1 + head];

    int start = g_off[node];
    int deg   = g_cnt[node];

    float w = __expf(leaky(ash + adh));   // self loop
    float sumw = w;
    float acc0, acc1, acc2, acc3;
    {
        uint2 u = *(const uint2*)&g_xw1h[node * F1 + fb];
        float2 f0 = __half22float2(*(__half2*)&u.x);
        float2 f1 = __half22float2(*(__half2*)&u.y);
        acc0 = w * f0.x; acc1 = w * f0.y; acc2 = w * f1.x; acc3 = w * f1.y;
    }
    bool hi_half = (lane >= 16);
#pragma unroll 4
    for (int j = 0; j < deg; j++) {
        int s = g_srcs[start + j];
        uint2 wv = g_w1e[start + j];
        unsigned wsel = hs ? wv.y : wv.x;
        float2 wf = __half22float2(*(__half2*)&wsel);
        float wj = hi_half ? wf.y : wf.x;
        sumw += wj;
        uint2 u = *(const uint2*)&g_xw1h[s * F1 + fb];
        float2 f0 = __half22float2(*(__half2*)&u.x);
        float2 f1 = __half22float2(*(__half2*)&u.y);
        acc0 += wj * f0.x; acc1 += wj * f0.y; acc2 += wj * f1.x; acc3 += wj * f1.y;
    }
    float inv = 1.f / sumw;
    float o0 = acc0 * inv + bias1[fb + 0];
    float o1 = acc1 * inv + bias1[fb + 1];
    float o2 = acc2 * inv + bias1[fb + 2];
    float o3 = acc3 * inv + bias1[fb + 3];
    o0 = o0 > 0.f ? o0 : expm1f(o0);
    o1 = o1 > 0.f ? o1 : expm1f(o1);
    o2 = o2 > 0.f ? o2 : expm1f(o2);
    o3 = o3 > 0.f ? o3 : expm1f(o3);
    __half2* xp = (__half2*)&g_x2h[node * F1 + fb];
    xp[0] = __floats2half2_rn(o0, o1);
    xp[1] = __floats2half2_rn(o2, o3);
}

// ---------------- GEMM2: xw2 = x2[n,256] @ W2[256,16] (fp16 in) ----------------
#define G2_ROWS 512
#define G2_BK   16
__global__ void __launch_bounds__(256) gemm2_kernel(
        const float* __restrict__ W2, int n) {
    __shared__ float Xs[G2_ROWS][G2_BK + 1];
    const int tid = threadIdx.x;
    const int rowblk = blockIdx.x * G2_ROWS;
    const int rbase = tid & 63;
    const int c0 = (tid >> 6) * 4;

    float acc[8][4];
#pragma unroll
    for (int i = 0; i < 8; i++)
#pragma unroll
        for (int j = 0; j < 4; j++) acc[i][j] = 0.f;

    for (int kb = 0; kb < F1; kb += G2_BK) {
#pragma unroll
        for (int i = 0; i < 8; i++) {
            int lr = (tid >> 2) + 64 * i;
            int gr = rowblk + lr;
            int kc = (tid & 3) * 4;
            float2 fa = make_float2(0.f, 0.f), fb = make_float2(0.f, 0.f);
            if (gr < n) {
                uint2 v = *(const uint2*)&g_x2h[gr * F1 + kb + kc];
                fa = __half22float2(*(__half2*)&v.x);
                fb = __half22float2(*(__half2*)&v.y);
            }
            Xs[lr][kc + 0] = fa.x;
            Xs[lr][kc + 1] = fa.y;
            Xs[lr][kc + 2] = fb.x;
            Xs[lr][kc + 3] = fb.y;
        }
        float4 wr[G2_BK];
#pragma unroll
        for (int k = 0; k < G2_BK; k++)
            wr[k] = *(const float4*)&W2[(kb + k) * NCLS + c0];
        __syncthreads();
#pragma unroll
        for (int k = 0; k < G2_BK; k++) {
#pragma unroll
            for (int i = 0; i < 8; i++) {
                float xv = Xs[rbase + 64 * i][k];
                acc[i][0] += xv * wr[k].x;
                acc[i][1] += xv * wr[k].y;
                acc[i][2] += xv * wr[k].z;
                acc[i][3] += xv * wr[k].w;
            }
        }
        __syncthreads();
    }
#pragma unroll
    for (int i = 0; i < 8; i++) {
        int gr = rowblk + rbase + 64 * i;
        if (gr < n)
            *(float4*)&g_xw2[gr * NCLS + c0] =
                make_float4(acc[i][0], acc[i][1], acc[i][2], acc[i][3]);
    }
}

// ---------------- att2: a2s/a2d dots (thread per node) ----------------
__global__ void att2_kernel(const float* __restrict__ as2,
                            const float* __restrict__ ad2, int n) {
    int node = blockIdx.x * blockDim.x + threadIdx.x;
    if (node >= n) return;
    float ps = 0.f, pd = 0.f;
#pragma unroll
    for (int q = 0; q < 4; q++) {
        float4 x = *(const float4*)&g_xw2[node * NCLS + q * 4];
        float4 s = *(const float4*)&as2[q * 4];
        float4 d = *(const float4*)&ad2[q * 4];
        ps += x.x*s.x + x.y*s.y + x.z*s.z + x.w*s.w;
        pd += x.x*d.x + x.y*d.y + x.z*d.z + x.w*d.w;
    }
    g_a2s[node] = ps;
    g_a2d[node] = pd;
}

// ---------------- w2e: layer2 edge weights (edge-parallel) ----------------
__global__ void w2e_kernel(const void* __restrict__ ei, int e, int n) {
    int i = blockIdx.x * blockDim.x + threadIdx.x;
    if (i < e) {
        int d = load_idx(ei, e, 1, i);
        int s = load_idx(ei, e, 0, i);
        if (d >= 0 && d < n && s >= 0 && s < n) {
            int p = g_epos[i];
            if (p >= 0 && p < MAXE)
                g_w2e[p] = __expf(leaky(g_a2s[s] + g_a2d[d]));
        }
    }
}

// ---------------- agg2 + final softmax (warp per node, 2 edges/iter) ----------------
__global__ void agg2_kernel(const float* __restrict__ bias2,
                            float* __restrict__ out, int n) {
    int node = (blockIdx.x * blockDim.x + threadIdx.x) >> 5;
    int lane = threadIdx.x & 31;
    if (node >= n) return;

    int half_ = lane >> 4;
    int c     = lane & 15;
    float sumw = 0.f, acc = 0.f;
    if (half_ == 0) {                  // self loop counted once
        float w = __expf(leaky(g_a2s[node] + g_a2d[node]));
        sumw = w;
        acc  = w * g_xw2[node * NCLS + c];
    }
    int start = g_off[node];
    int deg   = g_cnt[node];
#pragma unroll 4
    for (int j = half_; j < deg; j += 2) {
        int s = g_srcs[start + j];
        float wj = g_w2e[start + j];
        sumw += wj;
        acc  += wj * g_xw2[s * NCLS + c];
    }
    sumw += __shfl_xor_sync(0xffffffffu, sumw, 16);
    acc  += __shfl_xor_sync(0xffffffffu, acc, 16);

    float logit = acc / sumw + bias2[c];

    float mx = logit;
#pragma unroll
    for (int off = 8; off > 0; off >>= 1)
        mx = fmaxf(mx, __shfl_xor_sync(0xffffffffu, mx, off));
    float p = __expf(logit - mx);
    float s16 = p;
#pragma unroll
    for (int off = 8; off > 0; off >>= 1)
        s16 += __shfl_xor_sync(0xffffffffu, s16, off);
    if (lane < NCLS) out[node * NCLS + lane] = p / s16;
}

// ---------------- launch ----------------
extern "C" void kernel_launch(void* const* d_in, const int* in_sizes, int n_in,
                              void* d_out, int out_size) {
    const float* obs  = (const float*)d_in[0];
    const void*  ei   = d_in[1];
    const float* W1   = (const float*)d_in[2];
    const float* as1  = (const float*)d_in[3];
    const float* ad1  = (const float*)d_in[4];
    const float* b1   = (const float*)d_in[5];
    const float* W2   = (const float*)d_in[6];
    const float* as2  = (const float*)d_in[7];
    const float* ad2  = (const float*)d_in[8];
    const float* b2   = (const float*)d_in[9];
    float* out = (float*)d_out;

    int n = in_sizes[0] / NFEAT;
    int e = in_sizes[1] / 2;
    int m4 = n * NFEAT / 4;

    prep_kernel<<<(m4 + 255) / 256, 256>>>(obs, W1, ei, e, n, m4);          // 0
    hist_kernel<<<(e + 255) / 256, 256>>>(ei, e, n);                        // 1
    scan_kernel<<<1, SC_T>>>(n);                                            // 2
    gemm1_mma_kernel<<<dim3(F1 / 128, (n + 127) / 128), 256>>>(as1, ad1, n);// 3 (ncu slot)
    scatter_kernel<<<(e + 255) / 256, 256>>>(ei, e, n);                     // 4
    agg1_kernel<<<(n + 3) / 4, 256>>>(b1, n);                               // 5
    gemm2_kernel<<<(n + G2_ROWS - 1) / G2_ROWS, 256>>>(W2, n);              // 6
    att2_kernel<<<(n + 255) / 256, 256>>>(as2, ad2, n);                     // 7
    w2e_kernel<<<(e + 255) / 256, 256>>>(ei, e, n);                         // 8
    agg2_kernel<<<(n + 7) / 8, 256>>>(b2, out, n);                          // 9
}

// round 9
// speedup vs baseline: 1.3673x; 1.3673x over previous
#include <cuda_runtime.h>
#include <cuda_fp16.h>
#include <math.h>

// Problem constants (fixed by the dataset)
#define NFEAT 128
#define F1    256      // H1*NHID
#define H1    4
#define NHID  64
#define NCLS  16
#define MAXN  50048
#define MAXE  800000

#define NEG_SLOPE 0.2f

// ---------------- scratch (static __device__, no allocation) ----------------
__device__ __align__(16) __half g_obsh[MAXN * NFEAT];  // obs fp16 (tail rows stay 0)
__device__ __align__(16) __half g_w1h [NFEAT * F1];    // W1 fp16
__device__ __align__(16) __half g_xw1h[MAXN * F1];     // layer1 x@W1 (fp16)
__device__ __align__(16) __half g_x2h [MAXN * F1];     // layer1 output after ELU (fp16)
__device__ __align__(16) float g_a1s[MAXN * H1];
__device__ __align__(16) float g_a1d[MAXN * H1];
__device__ __align__(16) float g_xw2[MAXN * NCLS];
__device__ float g_a2s[MAXN];
__device__ float g_a2d[MAXN];
__device__ int   g_cnt[MAXN];
__device__ int   g_off[MAXN];
__device__ int   g_cur[MAXN];
__device__ int   g_srcs[MAXE];                 // src node id, bucketed by dst
__device__ int   g_epos[MAXE];                 // edge i -> CSR slot
__device__ __align__(8) uint2 g_w1e[MAXE];     // layer1 edge weights, fp16 x4 heads
__device__ float g_w2e[MAXE];                  // layer2 edge weights
__device__ int   g_is64;                       // 1 if edge_index delivered as int64
__device__ int   g_scan_blk;                   // ordered block id for lookback scan
__device__ unsigned int g_scan_state[64];      // (flag<<30)|sum

__device__ __forceinline__ float leaky(float x) {
    return x > 0.f ? x : NEG_SLOPE * x;
}

__device__ __forceinline__ int load_idx(const void* p, int e, int part, int i) {
    if (g_is64) {
        return (int)((const long long*)p)[(long long)part * e + i];
    } else {
        return ((const int*)p)[(long long)part * e + i];
    }
}

// ---------------- prep: conversions + zeroing + scan reset + dtype probe ----------------
__global__ void prep_kernel(const float* __restrict__ obs,
                            const float* __restrict__ W1,
                            const void* ei, int e, int n, int m4) {
    int i = blockIdx.x * blockDim.x + threadIdx.x;
    if (i < m4) {
        float4 v = *(const float4*)&obs[i * 4];
        __half2* dst = (__half2*)&g_obsh[i * 4];
        dst[0] = __floats2half2_rn(v.x, v.y);
        dst[1] = __floats2half2_rn(v.z, v.w);
    }
    if (i < NFEAT * F1 / 4) {
        float4 v = *(const float4*)&W1[i * 4];
        __half2* dst = (__half2*)&g_w1h[i * 4];
        dst[0] = __floats2half2_rn(v.x, v.y);
        dst[1] = __floats2half2_rn(v.z, v.w);
    }
    if (i < n) g_cnt[i] = 0;
    if (i < 64) g_scan_state[i] = 0;
    if (i == 0) {
        g_scan_blk = 0;
        const long long* p = (const long long*)ei;
        int ok64 = 1;
        int cnt = e < 32 ? e : 32;
        for (int k = 0; k < cnt; k++) {
            long long v = p[k];
            if (v < 0 || v >= (long long)n) { ok64 = 0; break; }
        }
        g_is64 = ok64;
    }
}

// ---------------- hist: degree histogram ----------------
__global__ void hist_kernel(const void* __restrict__ ei, int e, int n) {
    int i = blockIdx.x * blockDim.x + threadIdx.x;
    if (i < e) {
        int d = load_idx(ei, e, 1, i);
        if (d >= 0 && d < n) atomicAdd(&g_cnt[d], 1);
    }
}

// ---------------- decoupled-lookback scan (measured 12us in R7) ----------------
#define FLAG_A 0x40000000u
#define FLAG_P 0x80000000u
#define SUM_MASK 0x3FFFFFFFu
__global__ void scan_kernel(int n) {
    __shared__ int s[1024];
    __shared__ int s_bid;
    __shared__ int s_prefix;
    int t = threadIdx.x;
    if (t == 0) s_bid = atomicAdd(&g_scan_blk, 1);
    __syncthreads();
    int bid = s_bid;
    int gid = bid * 1024 + t;
    int x = (gid < n) ? g_cnt[gid] : 0;
    s[t] = x;
    __syncthreads();
#pragma unroll
    for (int off = 1; off < 1024; off <<= 1) {
        int v = (t >= off) ? s[t - off] : 0;
        __syncthreads();
        s[t] += v;
        __syncthreads();
    }
    int aggregate = s[1023];
    if (t == 0) {
        if (bid == 0) {
            __threadfence();
            atomicExch(&g_scan_state[0], FLAG_P | (unsigned)aggregate);
            s_prefix = 0;
        } else {
            __threadfence();
            atomicExch(&g_scan_state[bid], FLAG_A | (unsigned)aggregate);
            int running = 0;
            for (int p = bid - 1; p >= 0; p--) {
                unsigned st;
                do { st = atomicAdd(&g_scan_state[p], 0u); } while ((st & 0xC0000000u) == 0u);
                running += (int)(st & SUM_MASK);
                if (st & FLAG_P) break;
            }
            __threadfence();
            atomicExch(&g_scan_state[bid], FLAG_P | (unsigned)(running + aggregate));
            s_prefix = running;
        }
    }
    __syncthreads();
    if (gid < n) {
        int o = s_prefix + s[t] - x;
        g_off[gid] = o;
        g_cur[gid] = o;
    }
}

// ---------------- GEMM1 (HMMA + ldmatrix) + fused att1 ----------------
// A smem [128][72] row-major halves; B smem [64][136] ([k][n]) halves.
__global__ void __launch_bounds__(256, 2) gemm1_mma_kernel(
        const float* __restrict__ att_s, const float* __restrict__ att_d, int M) {
    __shared__ __half As[128][72];
    __shared__ __half Bs[64][136];
    __shared__ float ps_s[128][4];
    __shared__ float pd_s[128][4];
    const int tid  = threadIdx.x;
    const int wid  = tid >> 5;
    const int lane = tid & 31;
    const int wm = wid >> 2;
    const int wn = wid & 3;
    const int g  = lane >> 2;
    const int t  = lane & 3;
    const int row0 = blockIdx.y * 128;
    const int col0 = blockIdx.x * 128;

    float c[4][4][4];
#pragma unroll
    for (int mt = 0; mt < 4; mt++)
#pragma unroll
        for (int nt = 0; nt < 4; nt++)
#pragma unroll
            for (int q = 0; q < 4; q++) c[mt][nt][q] = 0.f;

    for (int kb = 0; kb < NFEAT; kb += 64) {
        // A tile: 128 rows x 64 k (uint2 coalesced)
#pragma unroll
        for (int i = 0; i < 8; i++) {
            int idx = tid + i * 256;
            int r = idx >> 4;
            int q = idx & 15;
            *(uint2*)&As[r][q * 4] =
                *(const uint2*)&g_obsh[(row0 + r) * NFEAT + kb + q * 4];
        }
        // B tile: 64 k x 128 n, [k][n] — coalesced uint2 stores, NO transpose
#pragma unroll
        for (int i = 0; i < 8; i++) {
            int idx = tid + i * 256;
            int kr = idx >> 5;
            int nq = idx & 31;
            *(uint2*)&Bs[kr][nq * 4] =
                *(const uint2*)&g_w1h[(kb + kr) * F1 + col0 + nq * 4];
        }
        __syncthreads();
#pragma unroll
        for (int ks = 0; ks < 64; ks += 16) {
            unsigned a[4][4];
#pragma unroll
            for (int mt = 0; mt < 4; mt++) {
                int mr = wm * 64 + mt * 16;
                unsigned addr = (unsigned)__cvta_generic_to_shared(
                    &As[mr + (lane & 15)][ks + 8 * (lane >> 4)]);
                asm volatile(
                    "ldmatrix.sync.aligned.m8n8.x4.shared.b16 {%0,%1,%2,%3}, [%4];"
                    : "=r"(a[mt][0]), "=r"(a[mt][1]), "=r"(a[mt][2]), "=r"(a[mt][3])
                    : "r"(addr));
            }
            unsigned b[4][2];
#pragma unroll
            for (int nt = 0; nt < 4; nt++) {
                int nc = wn * 32 + nt * 8;
                unsigned addr = (unsigned)__cvta_generic_to_shared(
                    &Bs[ks + (lane & 15)][nc]);
                asm volatile(
                    "ldmatrix.sync.aligned.m8n8.x2.trans.shared.b16 {%0,%1}, [%2];"
                    : "=r"(b[nt][0]), "=r"(b[nt][1])
                    : "r"(addr));
            }
#pragma unroll
            for (int mt = 0; mt < 4; mt++)
#pragma unroll
                for (int nt = 0; nt < 4; nt++) {
                    asm volatile(
                        "mma.sync.aligned.m16n8k16.row.col.f32.f16.f16.f32 "
                        "{%0,%1,%2,%3}, {%4,%5,%6,%7}, {%8,%9}, {%0,%1,%2,%3};\n"
                        : "+f"(c[mt][nt][0]), "+f"(c[mt][nt][1]),
                          "+f"(c[mt][nt][2]), "+f"(c[mt][nt][3])
                        : "r"(a[mt][0]), "r"(a[mt][1]), "r"(a[mt][2]), "r"(a[mt][3]),
                          "r"(b[nt][0]), "r"(b[nt][1]));
                }
        }
        __syncthreads();
    }

    // epilogue: store fp16 xw1 AND accumulate att dots per row
    float psr[8], pdr[8];
#pragma unroll
    for (int ri = 0; ri < 8; ri++) { psr[ri] = 0.f; pdr[ri] = 0.f; }

#pragma unroll
    for (int mt = 0; mt < 4; mt++) {
#pragma unroll
        for (int nt = 0; nt < 4; nt++) {
            int colg = col0 + wn * 32 + nt * 8 + t * 2;
            float a_s0 = att_s[colg], a_s1 = att_s[colg + 1];
            float a_d0 = att_d[colg], a_d1 = att_d[colg + 1];
            psr[mt*2+0] += c[mt][nt][0] * a_s0 + c[mt][nt][1] * a_s1;
            pdr[mt*2+0] += c[mt][nt][0] * a_d0 + c[mt][nt][1] * a_d1;
            psr[mt*2+1] += c[mt][nt][2] * a_s0 + c[mt][nt][3] * a_s1;
            pdr[mt*2+1] += c[mt][nt][2] * a_d0 + c[mt][nt][3] * a_d1;

            int row = row0 + wm * 64 + mt * 16 + g;
            if (row < M)
                *(__half2*)&g_xw1h[row * F1 + colg] =
                    __floats2half2_rn(c[mt][nt][0], c[mt][nt][1]);
            if (row + 8 < M)
                *(__half2*)&g_xw1h[(row + 8) * F1 + colg] =
                    __floats2half2_rn(c[mt][nt][2], c[mt][nt][3]);
        }
    }
#pragma unroll
    for (int ri = 0; ri < 8; ri++) {
        psr[ri] += __shfl_xor_sync(0xffffffffu, psr[ri], 1);
        psr[ri] += __shfl_xor_sync(0xffffffffu, psr[ri], 2);
        pdr[ri] += __shfl_xor_sync(0xffffffffu, pdr[ri], 1);
        pdr[ri] += __shfl_xor_sync(0xffffffffu, pdr[ri], 2);
    }
    if (t == 0) {
#pragma unroll
        for (int ri = 0; ri < 8; ri++) {
            int row = wm * 64 + (ri >> 1) * 16 + g + (ri & 1) * 8;
            ps_s[row][wn] = psr[ri];
            pd_s[row][wn] = pdr[ri];
        }
    }
    __syncthreads();
    if (tid < 128) {
        int node = row0 + tid;
        if (node < M) {
            int hb = blockIdx.x * 2;
            g_a1s[node * H1 + hb    ] = ps_s[tid][0] + ps_s[tid][1];
            g_a1s[node * H1 + hb + 1] = ps_s[tid][2] + ps_s[tid][3];
            g_a1d[node * H1 + hb    ] = pd_s[tid][0] + pd_s[tid][1];
            g_a1d[node * H1 + hb + 1] = pd_s[tid][2] + pd_s[tid][3];
        }
    }
}

// ---------------- scatter: bucket srcs by dst (plain) ----------------
__global__ void scatter_kernel(const void* __restrict__ ei, int e, int n) {
    int i = blockIdx.x * blockDim.x + threadIdx.x;
    if (i < e) {
        int d = load_idx(ei, e, 1, i);
        int s = load_idx(ei, e, 0, i);
        if (d >= 0 && d < n && s >= 0 && s < n) {
            int p = atomicAdd(&g_cur[d], 1);
            if (p >= 0 && p < MAXE) {
                g_srcs[p] = s;
                g_epos[i] = p;
            }
        }
    }
}

// ---------------- w1e: layer1 edge weights (edge-parallel, latency-tolerant) ----------------
__global__ void w1e_kernel(const void* __restrict__ ei, int e, int n) {
    int i = blockIdx.x * blockDim.x + threadIdx.x;
    if (i < e) {
        int d = load_idx(ei, e, 1, i);
        int s = load_idx(ei, e, 0, i);
        if (d >= 0 && d < n && s >= 0 && s < n) {
            int p = g_epos[i];
            if (p >= 0 && p < MAXE) {
                float4 as = *(const float4*)&g_a1s[s * H1];
                float4 ad = *(const float4*)&g_a1d[d * H1];
                float w0 = __expf(leaky(as.x + ad.x));
                float w1 = __expf(leaky(as.y + ad.y));
                float w2 = __expf(leaky(as.z + ad.z));
                float w3 = __expf(leaky(as.w + ad.w));
                __half2 h0 = __floats2half2_rn(w0, w1);
                __half2 h1 = __floats2half2_rn(w2, w3);
                uint2 packed;
                packed.x = *(unsigned*)&h0;
                packed.y = *(unsigned*)&h1;
                g_w1e[p] = packed;
            }
        }
    }
}

// ---------------- agg1: 2 warps/node; weights precomputed; bias + ELU ----------------
__global__ void agg1_kernel(const float* __restrict__ bias1, int n) {
    int w2 = (blockIdx.x * blockDim.x + threadIdx.x) >> 5;
    int node = w2 >> 1;
    int hs   = w2 & 1;
    int lane = threadIdx.x & 31;
    if (node >= n) return;

    int fb = hs * 128 + lane * 4;
    int head = fb >> 6;
    float adh = g_a1d[node * H1 + head];
    float ash = g_a1s[node * H1 + head];

    int start = g_off[node];
    int deg   = g_cnt[node];

    float w = __expf(leaky(ash + adh));   // self loop
    float sumw = w;
    float acc0, acc1, acc2, acc3;
    {
        uint2 u = *(const uint2*)&g_xw1h[node * F1 + fb];
        float2 f0 = __half22float2(*(__half2*)&u.x);
        float2 f1 = __half22float2(*(__half2*)&u.y);
        acc0 = w * f0.x; acc1 = w * f0.y; acc2 = w * f1.x; acc3 = w * f1.y;
    }
    bool hi_half = (lane >= 16);
#pragma unroll 4
    for (int j = 0; j < deg; j++) {
        int s = g_srcs[start + j];
        uint2 wv = g_w1e[start + j];
        unsigned wsel = hs ? wv.y : wv.x;
        float2 wf = __half22float2(*(__half2*)&wsel);
        float wj = hi_half ? wf.y : wf.x;
        sumw += wj;
        uint2 u = *(const uint2*)&g_xw1h[s * F1 + fb];
        float2 f0 = __half22float2(*(__half2*)&u.x);
        float2 f1 = __half22float2(*(__half2*)&u.y);
        acc0 += wj * f0.x; acc1 += wj * f0.y; acc2 += wj * f1.x; acc3 += wj * f1.y;
    }
    float inv = 1.f / sumw;
    float o0 = acc0 * inv + bias1[fb + 0];
    float o1 = acc1 * inv + bias1[fb + 1];
    float o2 = acc2 * inv + bias1[fb + 2];
    float o3 = acc3 * inv + bias1[fb + 3];
    o0 = o0 > 0.f ? o0 : expm1f(o0);
    o1 = o1 > 0.f ? o1 : expm1f(o1);
    o2 = o2 > 0.f ? o2 : expm1f(o2);
    o3 = o3 > 0.f ? o3 : expm1f(o3);
    __half2* xp = (__half2*)&g_x2h[node * F1 + fb];
    xp[0] = __floats2half2_rn(o0, o1);
    xp[1] = __floats2half2_rn(o2, o3);
}

// ---------------- GEMM2: xw2 = x2[n,256] @ W2[256,16] (fp16 in) ----------------
#define G2_ROWS 512
#define G2_BK   16
__global__ void __launch_bounds__(256) gemm2_kernel(
        const float* __restrict__ W2, int n) {
    __shared__ float Xs[G2_ROWS][G2_BK + 1];
    const int tid = threadIdx.x;
    const int rowblk = blockIdx.x * G2_ROWS;
    const int rbase = tid & 63;
    const int c0 = (tid >> 6) * 4;

    float acc[8][4];
#pragma unroll
    for (int i = 0; i < 8; i++)
#pragma unroll
        for (int j = 0; j < 4; j++) acc[i][j] = 0.f;

    for (int kb = 0; kb < F1; kb += G2_BK) {
#pragma unroll
        for (int i = 0; i < 8; i++) {
            int lr = (tid >> 2) + 64 * i;
            int gr = rowblk + lr;
            int kc = (tid & 3) * 4;
            float2 fa = make_float2(0.f, 0.f), fb = make_float2(0.f, 0.f);
            if (gr < n) {
                uint2 v = *(const uint2*)&g_x2h[gr * F1 + kb + kc];
                fa = __half22float2(*(__half2*)&v.x);
                fb = __half22float2(*(__half2*)&v.y);
            }
            Xs[lr][kc + 0] = fa.x;
            Xs[lr][kc + 1] = fa.y;
            Xs[lr][kc + 2] = fb.x;
            Xs[lr][kc + 3] = fb.y;
        }
        float4 wr[G2_BK];
#pragma unroll
        for (int k = 0; k < G2_BK; k++)
            wr[k] = *(const float4*)&W2[(kb + k) * NCLS + c0];
        __syncthreads();
#pragma unroll
        for (int k = 0; k < G2_BK; k++) {
#pragma unroll
            for (int i = 0; i < 8; i++) {
                float xv = Xs[rbase + 64 * i][k];
                acc[i][0] += xv * wr[k].x;
                acc[i][1] += xv * wr[k].y;
                acc[i][2] += xv * wr[k].z;
                acc[i][3] += xv * wr[k].w;
            }
        }
        __syncthreads();
    }
#pragma unroll
    for (int i = 0; i < 8; i++) {
        int gr = rowblk + rbase + 64 * i;
        if (gr < n)
            *(float4*)&g_xw2[gr * NCLS + c0] =
                make_float4(acc[i][0], acc[i][1], acc[i][2], acc[i][3]);
    }
}

// ---------------- att2: a2s/a2d dots (thread per node) ----------------
__global__ void att2_kernel(const float* __restrict__ as2,
                            const float* __restrict__ ad2, int n) {
    int node = blockIdx.x * blockDim.x + threadIdx.x;
    if (node >= n) return;
    float ps = 0.f, pd = 0.f;
#pragma unroll
    for (int q = 0; q < 4; q++) {
        float4 x = *(const float4*)&g_xw2[node * NCLS + q * 4];
        float4 s = *(const float4*)&as2[q * 4];
        float4 d = *(const float4*)&ad2[q * 4];
        ps += x.x*s.x + x.y*s.y + x.z*s.z + x.w*s.w;
        pd += x.x*d.x + x.y*d.y + x.z*d.z + x.w*d.w;
    }
    g_a2s[node] = ps;
    g_a2d[node] = pd;
}

// ---------------- w2e: layer2 edge weights (edge-parallel) ----------------
__global__ void w2e_kernel(const void* __restrict__ ei, int e, int n) {
    int i = blockIdx.x * blockDim.x + threadIdx.x;
    if (i < e) {
        int d = load_idx(ei, e, 1, i);
        int s = load_idx(ei, e, 0, i);
        if (d >= 0 && d < n && s >= 0 && s < n) {
            int p = g_epos[i];
            if (p >= 0 && p < MAXE)
                g_w2e[p] = __expf(leaky(g_a2s[s] + g_a2d[d]));
        }
    }
}

// ---------------- agg2 + final softmax (warp per node, 2 edges/iter) ----------------
__global__ void agg2_kernel(const float* __restrict__ bias2,
                            float* __restrict__ out, int n) {
    int node = (blockIdx.x * blockDim.x + threadIdx.x) >> 5;
    int lane = threadIdx.x & 31;
    if (node >= n) return;

    int half_ = lane >> 4;
    int c     = lane & 15;
    float sumw = 0.f, acc = 0.f;
    if (half_ == 0) {
        float w = __expf(leaky(g_a2s[node] + g_a2d[node]));
        sumw = w;
        acc  = w * g_xw2[node * NCLS + c];
    }
    int start = g_off[node];
    int deg   = g_cnt[node];
#pragma unroll 4
    for (int j = half_; j < deg; j += 2) {
        int s = g_srcs[start + j];
        float wj = g_w2e[start + j];
        sumw += wj;
        acc  += wj * g_xw2[s * NCLS + c];
    }
    sumw += __shfl_xor_sync(0xffffffffu, sumw, 16);
    acc  += __shfl_xor_sync(0xffffffffu, acc, 16);

    float logit = acc / sumw + bias2[c];

    float mx = logit;
#pragma unroll
    for (int off = 8; off > 0; off >>= 1)
        mx = fmaxf(mx, __shfl_xor_sync(0xffffffffu, mx, off));
    float p = __expf(logit - mx);
    float s16 = p;
#pragma unroll
    for (int off = 8; off > 0; off >>= 1)
        s16 += __shfl_xor_sync(0xffffffffu, s16, off);
    if (lane < NCLS) out[node * NCLS + lane] = p / s16;
}

// ---------------- launch ----------------
extern "C" void kernel_launch(void* const* d_in, const int* in_sizes, int n_in,
                              void* d_out, int out_size) {
    const float* obs  = (const float*)d_in[0];
    const void*  ei   = d_in[1];
    const float* W1   = (const float*)d_in[2];
    const float* as1  = (const float*)d_in[3];
    const float* ad1  = (const float*)d_in[4];
    const float* b1   = (const float*)d_in[5];
    const float* W2   = (const float*)d_in[6];
    const float* as2  = (const float*)d_in[7];
    const float* ad2  = (const float*)d_in[8];
    const float* b2   = (const float*)d_in[9];
    float* out = (float*)d_out;

    int n = in_sizes[0] / NFEAT;
    int e = in_sizes[1] / 2;
    int m4 = n * NFEAT / 4;
    int nb = (n + 1023) / 1024;

    prep_kernel<<<(m4 + 255) / 256, 256>>>(obs, W1, ei, e, n, m4);          // 0
    hist_kernel<<<(e + 255) / 256, 256>>>(ei, e, n);                        // 1
    scan_kernel<<<nb, 1024>>>(n);                                           // 2
    gemm1_mma_kernel<<<dim3(F1 / 128, (n + 127) / 128), 256>>>(as1, ad1, n);// 3 (ncu slot)
    scatter_kernel<<<(e + 255) / 256, 256>>>(ei, e, n);                     // 4
    w1e_kernel<<<(e + 255) / 256, 256>>>(ei, e, n);                         // 5
    agg1_kernel<<<(n + 3) / 4, 256>>>(b1, n);                               // 6
    gemm2_kernel<<<(n + G2_ROWS - 1) / G2_ROWS, 256>>>(W2, n);              // 7
    att2_kernel<<<(n + 255) / 256, 256>>>(as2, ad2, n);                     // 8
    w2e_kernel<<<(e + 255) / 256, 256>>>(ei, e, n);                         // 9
    agg2_kernel<<<(n + 7) / 8, 256>>>(b2, out, n);                          // 10
}

// round 10
// speedup vs baseline: 1.4764x; 1.0798x over previous
#include <cuda_runtime.h>
#include <cuda_fp16.h>
#include <math.h>

// Problem constants (fixed by the dataset)
#define NFEAT 128
#define F1    256      // H1*NHID
#define H1    4
#define NHID  64
#define NCLS  16
#define MAXN  50048
#define MAXE  800000

#define NEG_SLOPE 0.2f

// ---------------- scratch (static __device__, no allocation) ----------------
__device__ __align__(16) __half g_obsh[MAXN * NFEAT];  // obs fp16 (tail rows stay 0)
__device__ __align__(16) __half g_w1h [NFEAT * F1];    // W1 fp16
__device__ __align__(16) __half g_xw1h[MAXN * F1];     // layer1 x@W1 (fp16)
__device__ __align__(16) __half g_x2h [MAXN * F1];     // layer1 output after ELU (fp16)
__device__ __align__(16) float g_a1s[MAXN * H1];
__device__ __align__(16) float g_a1d[MAXN * H1];
__device__ __align__(16) float g_xw2[MAXN * NCLS];
__device__ float g_a2s[MAXN];
__device__ float g_a2d[MAXN];
__device__ int   g_cnt[MAXN];   // ZERO at entry of every run (BSS init + agg2 re-zeroes)
__device__ int   g_off[MAXN];
__device__ int   g_cur[MAXN];
__device__ int   g_srcs[MAXE];                 // src node id, bucketed by dst
__device__ int   g_epos[MAXE];                 // edge i -> CSR slot
__device__ __align__(8) uint2 g_w1e[MAXE];     // layer1 edge weights, fp16 x4 heads
__device__ float g_w2e[MAXE];                  // layer2 edge weights
__device__ int   g_scan_blk;                   // ordered block id for lookback scan
__device__ unsigned int g_scan_state[64];      // (flag<<30)|sum

__device__ __forceinline__ float leaky(float x) {
    return x > 0.f ? x : NEG_SLOPE * x;
}

// ---------------- prep: conversions + scan reset + FUSED histogram ----------------
// g_cnt is guaranteed zero at kernel entry (BSS on first run; agg2 re-zeroes after).
__global__ void prep_kernel(const float* __restrict__ obs,
                            const float* __restrict__ W1,
                            const int* __restrict__ ei, int e, int n, int m4) {
    int i = blockIdx.x * blockDim.x + threadIdx.x;
    if (i < m4) {
        float4 v = *(const float4*)&obs[i * 4];
        __half2* dst = (__half2*)&g_obsh[i * 4];
        dst[0] = __floats2half2_rn(v.x, v.y);
        dst[1] = __floats2half2_rn(v.z, v.w);
    }
    if (i < NFEAT * F1 / 4) {
        float4 v = *(const float4*)&W1[i * 4];
        __half2* dst = (__half2*)&g_w1h[i * 4];
        dst[0] = __floats2half2_rn(v.x, v.y);
        dst[1] = __floats2half2_rn(v.z, v.w);
    }
    if (i < 64) g_scan_state[i] = 0;
    if (i == 0) g_scan_blk = 0;
    if (i < e) {                       // histogram (edge_index is int32)
        int d = ei[e + i];
        if (d >= 0 && d < n) atomicAdd(&g_cnt[d], 1);
    }
}

// ---------------- decoupled-lookback scan ----------------
#define FLAG_A 0x40000000u
#define FLAG_P 0x80000000u
#define SUM_MASK 0x3FFFFFFFu
__global__ void scan_kernel(int n) {
    __shared__ int s[1024];
    __shared__ int s_bid;
    __shared__ int s_prefix;
    int t = threadIdx.x;
    if (t == 0) s_bid = atomicAdd(&g_scan_blk, 1);
    __syncthreads();
    int bid = s_bid;
    int gid = bid * 1024 + t;
    int x = (gid < n) ? g_cnt[gid] : 0;
    s[t] = x;
    __syncthreads();
#pragma unroll
    for (int off = 1; off < 1024; off <<= 1) {
        int v = (t >= off) ? s[t - off] : 0;
        __syncthreads();
        s[t] += v;
        __syncthreads();
    }
    int aggregate = s[1023];
    if (t == 0) {
        if (bid == 0) {
            __threadfence();
            atomicExch(&g_scan_state[0], FLAG_P | (unsigned)aggregate);
            s_prefix = 0;
        } else {
            __threadfence();
            atomicExch(&g_scan_state[bid], FLAG_A | (unsigned)aggregate);
            int running = 0;
            for (int p = bid - 1; p >= 0; p--) {
                unsigned st;
                do { st = atomicAdd(&g_scan_state[p], 0u); } while ((st & 0xC0000000u) == 0u);
                running += (int)(st & SUM_MASK);
                if (st & FLAG_P) break;
            }
            __threadfence();
            atomicExch(&g_scan_state[bid], FLAG_P | (unsigned)(running + aggregate));
            s_prefix = running;
        }
    }
    __syncthreads();
    if (gid < n) {
        int o = s_prefix + s[t] - x;
        g_off[gid] = o;
        g_cur[gid] = o;
    }
}

// ---------------- GEMM1 (HMMA + ldmatrix) + fused att1 ----------------
__global__ void __launch_bounds__(256, 2) gemm1_mma_kernel(
        const float* __restrict__ att_s, const float* __restrict__ att_d, int M) {
    __shared__ __half As[128][72];
    __shared__ __half Bs[64][136];
    __shared__ float ps_s[128][4];
    __shared__ float pd_s[128][4];
    const int tid  = threadIdx.x;
    const int wid  = tid >> 5;
    const int lane = tid & 31;
    const int wm = wid >> 2;
    const int wn = wid & 3;
    const int g  = lane >> 2;
    const int t  = lane & 3;
    const int row0 = blockIdx.y * 128;
    const int col0 = blockIdx.x * 128;

    float c[4][4][4];
#pragma unroll
    for (int mt = 0; mt < 4; mt++)
#pragma unroll
        for (int nt = 0; nt < 4; nt++)
#pragma unroll
            for (int q = 0; q < 4; q++) c[mt][nt][q] = 0.f;

    for (int kb = 0; kb < NFEAT; kb += 64) {
#pragma unroll
        for (int i = 0; i < 8; i++) {
            int idx = tid + i * 256;
            int r = idx >> 4;
            int q = idx & 15;
            *(uint2*)&As[r][q * 4] =
                *(const uint2*)&g_obsh[(row0 + r) * NFEAT + kb + q * 4];
        }
#pragma unroll
        for (int i = 0; i < 8; i++) {
            int idx = tid + i * 256;
            int kr = idx >> 5;
            int nq = idx & 31;
            *(uint2*)&Bs[kr][nq * 4] =
                *(const uint2*)&g_w1h[(kb + kr) * F1 + col0 + nq * 4];
        }
        __syncthreads();
#pragma unroll
        for (int ks = 0; ks < 64; ks += 16) {
            unsigned a[4][4];
#pragma unroll
            for (int mt = 0; mt < 4; mt++) {
                int mr = wm * 64 + mt * 16;
                unsigned addr = (unsigned)__cvta_generic_to_shared(
                    &As[mr + (lane & 15)][ks + 8 * (lane >> 4)]);
                asm volatile(
                    "ldmatrix.sync.aligned.m8n8.x4.shared.b16 {%0,%1,%2,%3}, [%4];"
                    : "=r"(a[mt][0]), "=r"(a[mt][1]), "=r"(a[mt][2]), "=r"(a[mt][3])
                    : "r"(addr));
            }
            unsigned b[4][2];
#pragma unroll
            for (int nt = 0; nt < 4; nt++) {
                int nc = wn * 32 + nt * 8;
                unsigned addr = (unsigned)__cvta_generic_to_shared(
                    &Bs[ks + (lane & 15)][nc]);
                asm volatile(
                    "ldmatrix.sync.aligned.m8n8.x2.trans.shared.b16 {%0,%1}, [%2];"
                    : "=r"(b[nt][0]), "=r"(b[nt][1])
                    : "r"(addr));
            }
#pragma unroll
            for (int mt = 0; mt < 4; mt++)
#pragma unroll
                for (int nt = 0; nt < 4; nt++) {
                    asm volatile(
                        "mma.sync.aligned.m16n8k16.row.col.f32.f16.f16.f32 "
                        "{%0,%1,%2,%3}, {%4,%5,%6,%7}, {%8,%9}, {%0,%1,%2,%3};\n"
                        : "+f"(c[mt][nt][0]), "+f"(c[mt][nt][1]),
                          "+f"(c[mt][nt][2]), "+f"(c[mt][nt][3])
                        : "r"(a[mt][0]), "r"(a[mt][1]), "r"(a[mt][2]), "r"(a[mt][3]),
                          "r"(b[nt][0]), "r"(b[nt][1]));
                }
        }
        __syncthreads();
    }

    float psr[8], pdr[8];
#pragma unroll
    for (int ri = 0; ri < 8; ri++) { psr[ri] = 0.f; pdr[ri] = 0.f; }

#pragma unroll
    for (int mt = 0; mt < 4; mt++) {
#pragma unroll
        for (int nt = 0; nt < 4; nt++) {
            int colg = col0 + wn * 32 + nt * 8 + t * 2;
            float a_s0 = att_s[colg], a_s1 = att_s[colg + 1];
            float a_d0 = att_d[colg], a_d1 = att_d[colg + 1];
            psr[mt*2+0] += c[mt][nt][0] * a_s0 + c[mt][nt][1] * a_s1;
            pdr[mt*2+0] += c[mt][nt][0] * a_d0 + c[mt][nt][1] * a_d1;
            psr[mt*2+1] += c[mt][nt][2] * a_s0 + c[mt][nt][3] * a_s1;
            pdr[mt*2+1] += c[mt][nt][2] * a_d0 + c[mt][nt][3] * a_d1;

            int row = row0 + wm * 64 + mt * 16 + g;
            if (row < M)
                *(__half2*)&g_xw1h[row * F1 + colg] =
                    __floats2half2_rn(c[mt][nt][0], c[mt][nt][1]);
            if (row + 8 < M)
                *(__half2*)&g_xw1h[(row + 8) * F1 + colg] =
                    __floats2half2_rn(c[mt][nt][2], c[mt][nt][3]);
        }
    }
#pragma unroll
    for (int ri = 0; ri < 8; ri++) {
        psr[ri] += __shfl_xor_sync(0xffffffffu, psr[ri], 1);
        psr[ri] += __shfl_xor_sync(0xffffffffu, psr[ri], 2);
        pdr[ri] += __shfl_xor_sync(0xffffffffu, pdr[ri], 1);
        pdr[ri] += __shfl_xor_sync(0xffffffffu, pdr[ri], 2);
    }
    if (t == 0) {
#pragma unroll
        for (int ri = 0; ri < 8; ri++) {
            int row = wm * 64 + (ri >> 1) * 16 + g + (ri & 1) * 8;
            ps_s[row][wn] = psr[ri];
            pd_s[row][wn] = pdr[ri];
        }
    }
    __syncthreads();
    if (tid < 128) {
        int node = row0 + tid;
        if (node < M) {
            int hb = blockIdx.x * 2;
            g_a1s[node * H1 + hb    ] = ps_s[tid][0] + ps_s[tid][1];
            g_a1s[node * H1 + hb + 1] = ps_s[tid][2] + ps_s[tid][3];
            g_a1d[node * H1 + hb    ] = pd_s[tid][0] + pd_s[tid][1];
            g_a1d[node * H1 + hb + 1] = pd_s[tid][2] + pd_s[tid][3];
        }
    }
}

// ---------------- scatter: bucket srcs by dst ----------------
__global__ void scatter_kernel(const int* __restrict__ ei, int e, int n) {
    int i = blockIdx.x * blockDim.x + threadIdx.x;
    if (i < e) {
        int d = ei[e + i];
        int s = ei[i];
        if (d >= 0 && d < n && s >= 0 && s < n) {
            int p = atomicAdd(&g_cur[d], 1);
            if (p >= 0 && p < MAXE) {
                g_srcs[p] = s;
                g_epos[i] = p;
            }
        }
    }
}

// ---------------- w1e: layer1 edge weights (edge-parallel) ----------------
__global__ void w1e_kernel(const int* __restrict__ ei, int e, int n) {
    int i = blockIdx.x * blockDim.x + threadIdx.x;
    if (i < e) {
        int d = ei[e + i];
        int s = ei[i];
        if (d >= 0 && d < n && s >= 0 && s < n) {
            int p = g_epos[i];
            if (p >= 0 && p < MAXE) {
                float4 as = *(const float4*)&g_a1s[s * H1];
                float4 ad = *(const float4*)&g_a1d[d * H1];
                float w0 = __expf(leaky(as.x + ad.x));
                float w1 = __expf(leaky(as.y + ad.y));
                float w2 = __expf(leaky(as.z + ad.z));
                float w3 = __expf(leaky(as.w + ad.w));
                __half2 h0 = __floats2half2_rn(w0, w1);
                __half2 h1 = __floats2half2_rn(w2, w3);
                uint2 packed;
                packed.x = *(unsigned*)&h0;
                packed.y = *(unsigned*)&h1;
                g_w1e[p] = packed;
            }
        }
    }
}

// ---------------- agg1: 2 warps/node; weights precomputed; bias + ELU ----------------
__global__ void agg1_kernel(const float* __restrict__ bias1, int n) {
    int w2 = (blockIdx.x * blockDim.x + threadIdx.x) >> 5;
    int node = w2 >> 1;
    int hs   = w2 & 1;
    int lane = threadIdx.x & 31;
    if (node >= n) return;

    int fb = hs * 128 + lane * 4;
    int head = fb >> 6;
    float adh = g_a1d[node * H1 + head];
    float ash = g_a1s[node * H1 + head];

    int start = g_off[node];
    int deg   = g_cnt[node];

    float w = __expf(leaky(ash + adh));   // self loop
    float sumw = w;
    float acc0, acc1, acc2, acc3;
    {
        uint2 u = *(const uint2*)&g_xw1h[node * F1 + fb];
        float2 f0 = __half22float2(*(__half2*)&u.x);
        float2 f1 = __half22float2(*(__half2*)&u.y);
        acc0 = w * f0.x; acc1 = w * f0.y; acc2 = w * f1.x; acc3 = w * f1.y;
    }
    bool hi_half = (lane >= 16);
#pragma unroll 4
    for (int j = 0; j < deg; j++) {
        int s = g_srcs[start + j];
        uint2 wv = g_w1e[start + j];
        unsigned wsel = hs ? wv.y : wv.x;
        float2 wf = __half22float2(*(__half2*)&wsel);
        float wj = hi_half ? wf.y : wf.x;
        sumw += wj;
        uint2 u = *(const uint2*)&g_xw1h[s * F1 + fb];
        float2 f0 = __half22float2(*(__half2*)&u.x);
        float2 f1 = __half22float2(*(__half2*)&u.y);
        acc0 += wj * f0.x; acc1 += wj * f0.y; acc2 += wj * f1.x; acc3 += wj * f1.y;
    }
    float inv = 1.f / sumw;
    float o0 = acc0 * inv + bias1[fb + 0];
    float o1 = acc1 * inv + bias1[fb + 1];
    float o2 = acc2 * inv + bias1[fb + 2];
    float o3 = acc3 * inv + bias1[fb + 3];
    o0 = o0 > 0.f ? o0 : expm1f(o0);
    o1 = o1 > 0.f ? o1 : expm1f(o1);
    o2 = o2 > 0.f ? o2 : expm1f(o2);
    o3 = o3 > 0.f ? o3 : expm1f(o3);
    __half2* xp = (__half2*)&g_x2h[node * F1 + fb];
    xp[0] = __floats2half2_rn(o0, o1);
    xp[1] = __floats2half2_rn(o2, o3);
}

// ---------------- GEMM2 + fused att2: 256 rows/block ----------------
#define G2_ROWS 256
__global__ void __launch_bounds__(256) gemm2_kernel(
        const float* __restrict__ W2,
        const float* __restrict__ as2, const float* __restrict__ ad2, int n) {
    __shared__ float Xs[G2_ROWS][17];
    __shared__ float ps_sm[G2_ROWS][4];
    __shared__ float pd_sm[G2_ROWS][4];
    const int tid = threadIdx.x;
    const int rowblk = blockIdx.x * G2_ROWS;
    const int rbase = tid & 63;
    const int cg = tid >> 6;
    const int c0 = cg * 4;

    float acc[4][4];
#pragma unroll
    for (int i = 0; i < 4; i++)
#pragma unroll
        for (int j = 0; j < 4; j++) acc[i][j] = 0.f;

    for (int kb = 0; kb < F1; kb += 16) {
#pragma unroll
        for (int i = 0; i < 4; i++) {
            int lr = (tid >> 2) + 64 * i;
            int gr = rowblk + lr;
            int kc = (tid & 3) * 4;
            float2 fa = make_float2(0.f, 0.f), fb = make_float2(0.f, 0.f);
            if (gr < n) {
                uint2 v = *(const uint2*)&g_x2h[gr * F1 + kb + kc];
                fa = __half22float2(*(__half2*)&v.x);
                fb = __half22float2(*(__half2*)&v.y);
            }
            Xs[lr][kc + 0] = fa.x;
            Xs[lr][kc + 1] = fa.y;
            Xs[lr][kc + 2] = fb.x;
            Xs[lr][kc + 3] = fb.y;
        }
        float4 wr[16];
#pragma unroll
        for (int k = 0; k < 16; k++)
            wr[k] = *(const float4*)&W2[(kb + k) * NCLS + c0];
        __syncthreads();
#pragma unroll
        for (int k = 0; k < 16; k++) {
#pragma unroll
            for (int i = 0; i < 4; i++) {
                float xv = Xs[rbase + 64 * i][k];
                acc[i][0] += xv * wr[k].x;
                acc[i][1] += xv * wr[k].y;
                acc[i][2] += xv * wr[k].z;
                acc[i][3] += xv * wr[k].w;
            }
        }
        __syncthreads();
    }
    // store xw2 + partial att2 dots
    float4 sv = *(const float4*)&as2[c0];
    float4 dv = *(const float4*)&ad2[c0];
#pragma unroll
    for (int i = 0; i < 4; i++) {
        int lr = rbase + 64 * i;
        int gr = rowblk + lr;
        if (gr < n)
            *(float4*)&g_xw2[gr * NCLS + c0] =
                make_float4(acc[i][0], acc[i][1], acc[i][2], acc[i][3]);
        ps_sm[lr][cg] = acc[i][0]*sv.x + acc[i][1]*sv.y + acc[i][2]*sv.z + acc[i][3]*sv.w;
        pd_sm[lr][cg] = acc[i][0]*dv.x + acc[i][1]*dv.y + acc[i][2]*dv.z + acc[i][3]*dv.w;
        __syncthreads();
        // nothing; keep loop structure sync-free below
    }
    __syncthreads();
    {
        int gr = rowblk + tid;
        if (tid < G2_ROWS && gr < n) {
            g_a2s[gr] = ps_sm[tid][0] + ps_sm[tid][1] + ps_sm[tid][2] + ps_sm[tid][3];
            g_a2d[gr] = pd_sm[tid][0] + pd_sm[tid][1] + pd_sm[tid][2] + pd_sm[tid][3];
        }
    }
}

// ---------------- w2e: layer2 edge weights (edge-parallel) ----------------
__global__ void w2e_kernel(const int* __restrict__ ei, int e, int n) {
    int i = blockIdx.x * blockDim.x + threadIdx.x;
    if (i < e) {
        int d = ei[e + i];
        int s = ei[i];
        if (d >= 0 && d < n && s >= 0 && s < n) {
            int p = g_epos[i];
            if (p >= 0 && p < MAXE)
                g_w2e[p] = __expf(leaky(g_a2s[s] + g_a2d[d]));
        }
    }
}

// ---------------- agg2 + final softmax + g_cnt re-zero for next run ----------------
__global__ void agg2_kernel(const float* __restrict__ bias2,
                            float* __restrict__ out, int n) {
    int node = (blockIdx.x * blockDim.x + threadIdx.x) >> 5;
    int lane = threadIdx.x & 31;
    if (node >= n) return;

    int half_ = lane >> 4;
    int c     = lane & 15;
    float sumw = 0.f, acc = 0.f;
    if (half_ == 0) {
        float w = __expf(leaky(g_a2s[node] + g_a2d[node]));
        sumw = w;
        acc  = w * g_xw2[node * NCLS + c];
    }
    int start = g_off[node];
    int deg   = g_cnt[node];
#pragma unroll 4
    for (int j = half_; j < deg; j += 2) {
        int s = g_srcs[start + j];
        float wj = g_w2e[start + j];
        sumw += wj;
        acc  += wj * g_xw2[s * NCLS + c];
    }
    sumw += __shfl_xor_sync(0xffffffffu, sumw, 16);
    acc  += __shfl_xor_sync(0xffffffffu, acc, 16);

    float logit = acc / sumw + bias2[c];

    float mx = logit;
#pragma unroll
    for (int off = 8; off > 0; off >>= 1)
        mx = fmaxf(mx, __shfl_xor_sync(0xffffffffu, mx, off));
    float p = __expf(logit - mx);
    float s16 = p;
#pragma unroll
    for (int off = 8; off > 0; off >>= 1)
        s16 += __shfl_xor_sync(0xffffffffu, s16, off);
    if (lane < NCLS) out[node * NCLS + lane] = p / s16;

    // re-zero this node's degree for the next run (deg already read above)
    if (lane == 0) g_cnt[node] = 0;
}

// ---------------- launch ----------------
extern "C" void kernel_launch(void* const* d_in, const int* in_sizes, int n_in,
                              void* d_out, int out_size) {
    const float* obs  = (const float*)d_in[0];
    const int*   ei   = (const int*)d_in[1];   // int32 (confirmed: int64 read crashes)
    const float* W1   = (const float*)d_in[2];
    const float* as1  = (const float*)d_in[3];
    const float* ad1  = (const float*)d_in[4];
    const float* b1   = (const float*)d_in[5];
    const float* W2   = (const float*)d_in[6];
    const float* as2  = (const float*)d_in[7];
    const float* ad2  = (const float*)d_in[8];
    const float* b2   = (const float*)d_in[9];
    float* out = (float*)d_out;

    int n = in_sizes[0] / NFEAT;
    int e = in_sizes[1] / 2;
    int m4 = n * NFEAT / 4;
    int nb = (n + 1023) / 1024;
    int prep_threads = m4 > e ? m4 : e;

    prep_kernel<<<(prep_threads + 255) / 256, 256>>>(obs, W1, ei, e, n, m4); // 0
    scan_kernel<<<nb, 1024>>>(n);                                            // 1
    gemm1_mma_kernel<<<dim3(F1 / 128, (n + 127) / 128), 256>>>(as1, ad1, n); // 2
    scatter_kernel<<<(e + 255) / 256, 256>>>(ei, e, n);                      // 3 (ncu slot)
    w1e_kernel<<<(e + 255) / 256, 256>>>(ei, e, n);                          // 4
    agg1_kernel<<<(n + 3) / 4, 256>>>(b1, n);                                // 5
    gemm2_kernel<<<(n + G2_ROWS - 1) / G2_ROWS, 256>>>(W2, as2, ad2, n);     // 6
    w2e_kernel<<<(e + 255) / 256, 256>>>(ei, e, n);                          // 7
    agg2_kernel<<<(n + 7) / 8, 256>>>(b2, out, n);                           // 8
}

// round 11
// speedup vs baseline: 1.5622x; 1.0581x over previous
#include <cuda_runtime.h>
#include <cuda_fp16.h>
#include <math.h>

// Problem constants (fixed by the dataset)
#define NFEAT 128
#define F1    256      // H1*NHID
#define H1    4
#define NHID  64
#define NCLS  16
#define MAXN  50048
#define MAXE  800000
#define EK    96       // fixed bucket stride (max in-degree; Poisson(16) => P(>=96) ~ 1e-40)

#define NEG_SLOPE 0.2f

// ---------------- scratch (static __device__, no allocation) ----------------
__device__ __align__(16) __half g_obsh[MAXN * NFEAT];  // obs fp16 (tail rows stay 0)
__device__ __align__(16) __half g_w1h [NFEAT * F1];    // W1 fp16
__device__ __align__(16) __half g_xw1h[MAXN * F1];     // layer1 x@W1 (fp16)
__device__ __align__(16) __half g_x2h [MAXN * F1];     // layer1 output after ELU (fp16)
__device__ __align__(16) float g_a1s[MAXN * H1];
__device__ __align__(16) float g_a1d[MAXN * H1];
__device__ __align__(16) float g_xw2[MAXN * NCLS];
__device__ float g_a2s[MAXN];
__device__ float g_a2d[MAXN];
__device__ int   g_cnt[MAXN];                  // ZERO at entry (BSS + agg2 re-zeroes)
__device__ int   g_srcs[MAXN * EK];            // src ids, fixed-stride buckets
__device__ int   g_epos[MAXE];                 // prep: rank; sw1e: final slot (or -1)
__device__ __align__(8) uint2 g_w1e[MAXN * EK];// layer1 edge weights, fp16 x4 heads
__device__ float g_w2e[MAXN * EK];             // layer2 edge weights

__device__ __forceinline__ float leaky(float x) {
    return x > 0.f ? x : NEG_SLOPE * x;
}

// ---------------- prep: conversions + histogram with rank capture ----------------
__global__ void prep_kernel(const float* __restrict__ obs,
                            const float* __restrict__ W1,
                            const int* __restrict__ ei, int e, int n, int m4) {
    int i = blockIdx.x * blockDim.x + threadIdx.x;
    if (i < m4) {
        float4 v = *(const float4*)&obs[i * 4];
        __half2* dst = (__half2*)&g_obsh[i * 4];
        dst[0] = __floats2half2_rn(v.x, v.y);
        dst[1] = __floats2half2_rn(v.z, v.w);
    }
    if (i < NFEAT * F1 / 4) {
        float4 v = *(const float4*)&W1[i * 4];
        __half2* dst = (__half2*)&g_w1h[i * 4];
        dst[0] = __floats2half2_rn(v.x, v.y);
        dst[1] = __floats2half2_rn(v.z, v.w);
    }
    if (i < e) {                       // histogram; atomic return value = rank in bucket
        int d = ei[e + i];
        if (d >= 0 && d < n) {
            g_epos[i] = atomicAdd(&g_cnt[d], 1);
        } else {
            g_epos[i] = -1;
        }
    }
}

// ---------------- GEMM1 (HMMA + ldmatrix) + fused att1 ----------------
__global__ void __launch_bounds__(256, 2) gemm1_mma_kernel(
        const float* __restrict__ att_s, const float* __restrict__ att_d, int M) {
    __shared__ __half As[128][72];
    __shared__ __half Bs[64][136];
    __shared__ float ps_s[128][4];
    __shared__ float pd_s[128][4];
    const int tid  = threadIdx.x;
    const int wid  = tid >> 5;
    const int lane = tid & 31;
    const int wm = wid >> 2;
    const int wn = wid & 3;
    const int g  = lane >> 2;
    const int t  = lane & 3;
    const int row0 = blockIdx.y * 128;
    const int col0 = blockIdx.x * 128;

    float c[4][4][4];
#pragma unroll
    for (int mt = 0; mt < 4; mt++)
#pragma unroll
        for (int nt = 0; nt < 4; nt++)
#pragma unroll
            for (int q = 0; q < 4; q++) c[mt][nt][q] = 0.f;

    for (int kb = 0; kb < NFEAT; kb += 64) {
#pragma unroll
        for (int i = 0; i < 8; i++) {
            int idx = tid + i * 256;
            int r = idx >> 4;
            int q = idx & 15;
            *(uint2*)&As[r][q * 4] =
                *(const uint2*)&g_obsh[(row0 + r) * NFEAT + kb + q * 4];
        }
#pragma unroll
        for (int i = 0; i < 8; i++) {
            int idx = tid + i * 256;
            int kr = idx >> 5;
            int nq = idx & 31;
            *(uint2*)&Bs[kr][nq * 4] =
                *(const uint2*)&g_w1h[(kb + kr) * F1 + col0 + nq * 4];
        }
        __syncthreads();
#pragma unroll
        for (int ks = 0; ks < 64; ks += 16) {
            unsigned a[4][4];
#pragma unroll
            for (int mt = 0; mt < 4; mt++) {
                int mr = wm * 64 + mt * 16;
                unsigned addr = (unsigned)__cvta_generic_to_shared(
                    &As[mr + (lane & 15)][ks + 8 * (lane >> 4)]);
                asm volatile(
                    "ldmatrix.sync.aligned.m8n8.x4.shared.b16 {%0,%1,%2,%3}, [%4];"
                    : "=r"(a[mt][0]), "=r"(a[mt][1]), "=r"(a[mt][2]), "=r"(a[mt][3])
                    : "r"(addr));
            }
            unsigned b[4][2];
#pragma unroll
            for (int nt = 0; nt < 4; nt++) {
                int nc = wn * 32 + nt * 8;
                unsigned addr = (unsigned)__cvta_generic_to_shared(
                    &Bs[ks + (lane & 15)][nc]);
                asm volatile(
                    "ldmatrix.sync.aligned.m8n8.x2.trans.shared.b16 {%0,%1}, [%2];"
                    : "=r"(b[nt][0]), "=r"(b[nt][1])
                    : "r"(addr));
            }
#pragma unroll
            for (int mt = 0; mt < 4; mt++)
#pragma unroll
                for (int nt = 0; nt < 4; nt++) {
                    asm volatile(
                        "mma.sync.aligned.m16n8k16.row.col.f32.f16.f16.f32 "
                        "{%0,%1,%2,%3}, {%4,%5,%6,%7}, {%8,%9}, {%0,%1,%2,%3};\n"
                        : "+f"(c[mt][nt][0]), "+f"(c[mt][nt][1]),
                          "+f"(c[mt][nt][2]), "+f"(c[mt][nt][3])
                        : "r"(a[mt][0]), "r"(a[mt][1]), "r"(a[mt][2]), "r"(a[mt][3]),
                          "r"(b[nt][0]), "r"(b[nt][1]));
                }
        }
        __syncthreads();
    }

    float psr[8], pdr[8];
#pragma unroll
    for (int ri = 0; ri < 8; ri++) { psr[ri] = 0.f; pdr[ri] = 0.f; }

#pragma unroll
    for (int mt = 0; mt < 4; mt++) {
#pragma unroll
        for (int nt = 0; nt < 4; nt++) {
            int colg = col0 + wn * 32 + nt * 8 + t * 2;
            float a_s0 = att_s[colg], a_s1 = att_s[colg + 1];
            float a_d0 = att_d[colg], a_d1 = att_d[colg + 1];
            psr[mt*2+0] += c[mt][nt][0] * a_s0 + c[mt][nt][1] * a_s1;
            pdr[mt*2+0] += c[mt][nt][0] * a_d0 + c[mt][nt][1] * a_d1;
            psr[mt*2+1] += c[mt][nt][2] * a_s0 + c[mt][nt][3] * a_s1;
            pdr[mt*2+1] += c[mt][nt][2] * a_d0 + c[mt][nt][3] * a_d1;

            int row = row0 + wm * 64 + mt * 16 + g;
            if (row < M)
                *(__half2*)&g_xw1h[row * F1 + colg] =
                    __floats2half2_rn(c[mt][nt][0], c[mt][nt][1]);
            if (row + 8 < M)
                *(__half2*)&g_xw1h[(row + 8) * F1 + colg] =
                    __floats2half2_rn(c[mt][nt][2], c[mt][nt][3]);
        }
    }
#pragma unroll
    for (int ri = 0; ri < 8; ri++) {
        psr[ri] += __shfl_xor_sync(0xffffffffu, psr[ri], 1);
        psr[ri] += __shfl_xor_sync(0xffffffffu, psr[ri], 2);
        pdr[ri] += __shfl_xor_sync(0xffffffffu, pdr[ri], 1);
        pdr[ri] += __shfl_xor_sync(0xffffffffu, pdr[ri], 2);
    }
    if (t == 0) {
#pragma unroll
        for (int ri = 0; ri < 8; ri++) {
            int row = wm * 64 + (ri >> 1) * 16 + g + (ri & 1) * 8;
            ps_s[row][wn] = psr[ri];
            pd_s[row][wn] = pdr[ri];
        }
    }
    __syncthreads();
    if (tid < 128) {
        int node = row0 + tid;
        if (node < M) {
            int hb = blockIdx.x * 2;
            g_a1s[node * H1 + hb    ] = ps_s[tid][0] + ps_s[tid][1];
            g_a1s[node * H1 + hb + 1] = ps_s[tid][2] + ps_s[tid][3];
            g_a1d[node * H1 + hb    ] = pd_s[tid][0] + pd_s[tid][1];
            g_a1d[node * H1 + hb + 1] = pd_s[tid][2] + pd_s[tid][3];
        }
    }
}

// ---------------- sw1e: fill buckets (src + layer1 weights); no atomics ----------------
__global__ void sw1e_kernel(const int* __restrict__ ei, int e, int n) {
    int i = blockIdx.x * blockDim.x + threadIdx.x;
    if (i < e) {
        int d = ei[e + i];
        int s = ei[i];
        int rank = g_epos[i];
        if (d >= 0 && d < n && s >= 0 && s < n && rank >= 0 && rank < EK) {
            int p = d * EK + rank;
            g_srcs[p] = s;
            g_epos[i] = p;
            float4 as = *(const float4*)&g_a1s[s * H1];
            float4 ad = *(const float4*)&g_a1d[d * H1];
            float w0 = __expf(leaky(as.x + ad.x));
            float w1 = __expf(leaky(as.y + ad.y));
            float w2 = __expf(leaky(as.z + ad.z));
            float w3 = __expf(leaky(as.w + ad.w));
            __half2 h0 = __floats2half2_rn(w0, w1);
            __half2 h1 = __floats2half2_rn(w2, w3);
            uint2 packed;
            packed.x = *(unsigned*)&h0;
            packed.y = *(unsigned*)&h1;
            g_w1e[p] = packed;
        } else {
            g_epos[i] = -1;
        }
    }
}

// ---------------- agg1: 2 warps/node; weights precomputed; bias + ELU ----------------
__global__ void agg1_kernel(const float* __restrict__ bias1, int n) {
    int w2 = (blockIdx.x * blockDim.x + threadIdx.x) >> 5;
    int node = w2 >> 1;
    int hs   = w2 & 1;
    int lane = threadIdx.x & 31;
    if (node >= n) return;

    int fb = hs * 128 + lane * 4;
    int head = fb >> 6;
    float adh = g_a1d[node * H1 + head];
    float ash = g_a1s[node * H1 + head];

    int start = node * EK;
    int deg   = g_cnt[node];
    deg = deg < EK ? deg : EK;

    float w = __expf(leaky(ash + adh));   // self loop
    float sumw = w;
    float acc0, acc1, acc2, acc3;
    {
        uint2 u = *(const uint2*)&g_xw1h[node * F1 + fb];
        float2 f0 = __half22float2(*(__half2*)&u.x);
        float2 f1 = __half22float2(*(__half2*)&u.y);
        acc0 = w * f0.x; acc1 = w * f0.y; acc2 = w * f1.x; acc3 = w * f1.y;
    }
    bool hi_half = (lane >= 16);
#pragma unroll 8
    for (int j = 0; j < deg; j++) {
        int s = g_srcs[start + j];
        uint2 wv = g_w1e[start + j];
        unsigned wsel = hs ? wv.y : wv.x;
        float2 wf = __half22float2(*(__half2*)&wsel);
        float wj = hi_half ? wf.y : wf.x;
        sumw += wj;
        uint2 u = *(const uint2*)&g_xw1h[s * F1 + fb];
        float2 f0 = __half22float2(*(__half2*)&u.x);
        float2 f1 = __half22float2(*(__half2*)&u.y);
        acc0 += wj * f0.x; acc1 += wj * f0.y; acc2 += wj * f1.x; acc3 += wj * f1.y;
    }
    float inv = 1.f / sumw;
    float o0 = acc0 * inv + bias1[fb + 0];
    float o1 = acc1 * inv + bias1[fb + 1];
    float o2 = acc2 * inv + bias1[fb + 2];
    float o3 = acc3 * inv + bias1[fb + 3];
    o0 = o0 > 0.f ? o0 : expm1f(o0);
    o1 = o1 > 0.f ? o1 : expm1f(o1);
    o2 = o2 > 0.f ? o2 : expm1f(o2);
    o3 = o3 > 0.f ? o3 : expm1f(o3);
    __half2* xp = (__half2*)&g_x2h[node * F1 + fb];
    xp[0] = __floats2half2_rn(o0, o1);
    xp[1] = __floats2half2_rn(o2, o3);
}

// ---------------- GEMM2 + fused att2: 256 rows/block ----------------
#define G2_ROWS 256
__global__ void __launch_bounds__(256) gemm2_kernel(
        const float* __restrict__ W2,
        const float* __restrict__ as2, const float* __restrict__ ad2, int n) {
    __shared__ float Xs[G2_ROWS][17];
    __shared__ float ps_sm[G2_ROWS][4];
    __shared__ float pd_sm[G2_ROWS][4];
    const int tid = threadIdx.x;
    const int rowblk = blockIdx.x * G2_ROWS;
    const int rbase = tid & 63;
    const int cg = tid >> 6;
    const int c0 = cg * 4;

    float acc[4][4];
#pragma unroll
    for (int i = 0; i < 4; i++)
#pragma unroll
        for (int j = 0; j < 4; j++) acc[i][j] = 0.f;

    for (int kb = 0; kb < F1; kb += 16) {
#pragma unroll
        for (int i = 0; i < 4; i++) {
            int lr = (tid >> 2) + 64 * i;
            int gr = rowblk + lr;
            int kc = (tid & 3) * 4;
            float2 fa = make_float2(0.f, 0.f), fb = make_float2(0.f, 0.f);
            if (gr < n) {
                uint2 v = *(const uint2*)&g_x2h[gr * F1 + kb + kc];
                fa = __half22float2(*(__half2*)&v.x);
                fb = __half22float2(*(__half2*)&v.y);
            }
            Xs[lr][kc + 0] = fa.x;
            Xs[lr][kc + 1] = fa.y;
            Xs[lr][kc + 2] = fb.x;
            Xs[lr][kc + 3] = fb.y;
        }
        float4 wr[16];
#pragma unroll
        for (int k = 0; k < 16; k++)
            wr[k] = *(const float4*)&W2[(kb + k) * NCLS + c0];
        __syncthreads();
#pragma unroll
        for (int k = 0; k < 16; k++) {
#pragma unroll
            for (int i = 0; i < 4; i++) {
                float xv = Xs[rbase + 64 * i][k];
                acc[i][0] += xv * wr[k].x;
                acc[i][1] += xv * wr[k].y;
                acc[i][2] += xv * wr[k].z;
                acc[i][3] += xv * wr[k].w;
            }
        }
        __syncthreads();
    }
    // store xw2 + partial att2 dots
    float4 sv = *(const float4*)&as2[c0];
    float4 dv = *(const float4*)&ad2[c0];
#pragma unroll
    for (int i = 0; i < 4; i++) {
        int lr = rbase + 64 * i;
        int gr = rowblk + lr;
        if (gr < n)
            *(float4*)&g_xw2[gr * NCLS + c0] =
                make_float4(acc[i][0], acc[i][1], acc[i][2], acc[i][3]);
        ps_sm[lr][cg] = acc[i][0]*sv.x + acc[i][1]*sv.y + acc[i][2]*sv.z + acc[i][3]*sv.w;
        pd_sm[lr][cg] = acc[i][0]*dv.x + acc[i][1]*dv.y + acc[i][2]*dv.z + acc[i][3]*dv.w;
    }
    __syncthreads();
    {
        int gr = rowblk + tid;
        if (tid < G2_ROWS && gr < n) {
            g_a2s[gr] = ps_sm[tid][0] + ps_sm[tid][1] + ps_sm[tid][2] + ps_sm[tid][3];
            g_a2d[gr] = pd_sm[tid][0] + pd_sm[tid][1] + pd_sm[tid][2] + pd_sm[tid][3];
        }
    }
}

// ---------------- w2e: layer2 edge weights (edge-parallel) ----------------
__global__ void w2e_kernel(const int* __restrict__ ei, int e, int n) {
    int i = blockIdx.x * blockDim.x + threadIdx.x;
    if (i < e) {
        int p = g_epos[i];
        if (p >= 0 && p < MAXN * EK) {
            int d = ei[e + i];
            int s = ei[i];
            g_w2e[p] = __expf(leaky(g_a2s[s] + g_a2d[d]));
        }
    }
}

// ---------------- agg2 + final softmax + g_cnt re-zero for next run ----------------
__global__ void agg2_kernel(const float* __restrict__ bias2,
                            float* __restrict__ out, int n) {
    int node = (blockIdx.x * blockDim.x + threadIdx.x) >> 5;
    int lane = threadIdx.x & 31;
    if (node >= n) return;

    int half_ = lane >> 4;
    int c     = lane & 15;
    float sumw = 0.f, acc = 0.f;
    if (half_ == 0) {
        float w = __expf(leaky(g_a2s[node] + g_a2d[node]));
        sumw = w;
        acc  = w * g_xw2[node * NCLS + c];
    }
    int start = node * EK;
    int deg   = g_cnt[node];
    deg = deg < EK ? deg : EK;
#pragma unroll 4
    for (int j = half_; j < deg; j += 2) {
        int s = g_srcs[start + j];
        float wj = g_w2e[start + j];
        sumw += wj;
        acc  += wj * g_xw2[s * NCLS + c];
    }
    sumw += __shfl_xor_sync(0xffffffffu, sumw, 16);
    acc  += __shfl_xor_sync(0xffffffffu, acc, 16);

    float logit = acc / sumw + bias2[c];

    float mx = logit;
#pragma unroll
    for (int off = 8; off > 0; off >>= 1)
        mx = fmaxf(mx, __shfl_xor_sync(0xffffffffu, mx, off));
    float p = __expf(logit - mx);
    float s16 = p;
#pragma unroll
    for (int off = 8; off > 0; off >>= 1)
        s16 += __shfl_xor_sync(0xffffffffu, s16, off);
    if (lane < NCLS) out[node * NCLS + lane] = p / s16;

    // re-zero this node's degree for the next run (deg already read above)
    if (lane == 0) g_cnt[node] = 0;
}

// ---------------- launch ----------------
extern "C" void kernel_launch(void* const* d_in, const int* in_sizes, int n_in,
                              void* d_out, int out_size) {
    const float* obs  = (const float*)d_in[0];
    const int*   ei   = (const int*)d_in[1];   // int32 (confirmed: int64 read crashes)
    const float* W1   = (const float*)d_in[2];
    const float* as1  = (const float*)d_in[3];
    const float* ad1  = (const float*)d_in[4];
    const float* b1   = (const float*)d_in[5];
    const float* W2   = (const float*)d_in[6];
    const float* as2  = (const float*)d_in[7];
    const float* ad2  = (const float*)d_in[8];
    const float* b2   = (const float*)d_in[9];
    float* out = (float*)d_out;

    int n = in_sizes[0] / NFEAT;
    int e = in_sizes[1] / 2;
    int m4 = n * NFEAT / 4;
    int prep_threads = m4 > e ? m4 : e;

    prep_kernel<<<(prep_threads + 255) / 256, 256>>>(obs, W1, ei, e, n, m4); // 0
    gemm1_mma_kernel<<<dim3(F1 / 128, (n + 127) / 128), 256>>>(as1, ad1, n); // 1
    sw1e_kernel<<<(e + 255) / 256, 256>>>(ei, e, n);                         // 2
    agg1_kernel<<<(n + 3) / 4, 256>>>(b1, n);                                // 3 (ncu slot)
    gemm2_kernel<<<(n + G2_ROWS - 1) / G2_ROWS, 256>>>(W2, as2, ad2, n);     // 4
    w2e_kernel<<<(e + 255) / 256, 256>>>(ei, e, n);                          // 5
    agg2_kernel<<<(n + 7) / 8, 256>>>(b2, out, n);                           // 6
}

// round 12
// speedup vs baseline: 1.6947x; 1.0849x over previous
#include <cuda_runtime.h>
#include <cuda_fp16.h>
#include <math.h>

// Problem constants (fixed by the dataset)
#define NFEAT 128
#define F1    256      // H1*NHID
#define H1    4
#define NHID  64
#define NCLS  16
#define MAXN  50048
#define MAXE  800000
#define EK    96       // fixed bucket stride (max in-degree; Poisson(16) => P(>=96) ~ 1e-40)

#define NEG_SLOPE 0.2f

// ---------------- scratch (static __device__, no allocation) ----------------
__device__ __align__(16) __half g_obsh[MAXN * NFEAT];  // obs fp16 (tail rows stay 0)
__device__ __align__(16) __half g_w1h [NFEAT * F1];    // W1 fp16
__device__ __align__(16) __half g_xw1h[MAXN * F1];     // layer1 x@W1 (fp16)
__device__ __align__(16) __half g_x2h [MAXN * F1];     // layer1 output after ELU (fp16)
__device__ __align__(16) float g_a1s[MAXN * H1];
__device__ __align__(16) float g_a1d[MAXN * H1];
__device__ __align__(16) float g_xw2[MAXN * NCLS];
__device__ float g_a2s[MAXN];
__device__ float g_a2d[MAXN];
__device__ int   g_cnt[MAXN];                  // ZERO at entry (BSS + agg2 re-zeroes)
__device__ int   g_srcs[MAXN * EK];            // src ids, fixed-stride buckets
__device__ int   g_epos[MAXE];                 // prep: rank; sw1e: final slot (or -1)
__device__ __align__(8) uint2 g_w1e[MAXN * EK];// layer1 edge weights, fp16 x4 heads
__device__ float g_w2e[MAXN * EK];             // layer2 edge weights

__device__ __forceinline__ float leaky(float x) {
    return x > 0.f ? x : NEG_SLOPE * x;
}

// ---------------- prep: conversions + histogram with rank capture ----------------
__global__ void prep_kernel(const float* __restrict__ obs,
                            const float* __restrict__ W1,
                            const int* __restrict__ ei, int e, int n, int m4) {
    int i = blockIdx.x * blockDim.x + threadIdx.x;
    if (i < m4) {
        float4 v = *(const float4*)&obs[i * 4];
        __half2* dst = (__half2*)&g_obsh[i * 4];
        dst[0] = __floats2half2_rn(v.x, v.y);
        dst[1] = __floats2half2_rn(v.z, v.w);
    }
    if (i < NFEAT * F1 / 4) {
        float4 v = *(const float4*)&W1[i * 4];
        __half2* dst = (__half2*)&g_w1h[i * 4];
        dst[0] = __floats2half2_rn(v.x, v.y);
        dst[1] = __floats2half2_rn(v.z, v.w);
    }
    if (i < e) {                       // histogram; atomic return value = rank in bucket
        int d = ei[e + i];
        if (d >= 0 && d < n) {
            g_epos[i] = atomicAdd(&g_cnt[d], 1);
        } else {
            g_epos[i] = -1;
        }
    }
}

// ---------------- GEMM1 (HMMA + ldmatrix) + fused att1 ----------------
__global__ void __launch_bounds__(256, 2) gemm1_mma_kernel(
        const float* __restrict__ att_s, const float* __restrict__ att_d, int M) {
    __shared__ __half As[128][72];
    __shared__ __half Bs[64][136];
    __shared__ float ps_s[128][4];
    __shared__ float pd_s[128][4];
    const int tid  = threadIdx.x;
    const int wid  = tid >> 5;
    const int lane = tid & 31;
    const int wm = wid >> 2;
    const int wn = wid & 3;
    const int g  = lane >> 2;
    const int t  = lane & 3;
    const int row0 = blockIdx.y * 128;
    const int col0 = blockIdx.x * 128;

    float c[4][4][4];
#pragma unroll
    for (int mt = 0; mt < 4; mt++)
#pragma unroll
        for (int nt = 0; nt < 4; nt++)
#pragma unroll
            for (int q = 0; q < 4; q++) c[mt][nt][q] = 0.f;

    for (int kb = 0; kb < NFEAT; kb += 64) {
#pragma unroll
        for (int i = 0; i < 8; i++) {
            int idx = tid + i * 256;
            int r = idx >> 4;
            int q = idx & 15;
            *(uint2*)&As[r][q * 4] =
                *(const uint2*)&g_obsh[(row0 + r) * NFEAT + kb + q * 4];
        }
#pragma unroll
        for (int i = 0; i < 8; i++) {
            int idx = tid + i * 256;
            int kr = idx >> 5;
            int nq = idx & 31;
            *(uint2*)&Bs[kr][nq * 4] =
                *(const uint2*)&g_w1h[(kb + kr) * F1 + col0 + nq * 4];
        }
        __syncthreads();
#pragma unroll
        for (int ks = 0; ks < 64; ks += 16) {
            unsigned a[4][4];
#pragma unroll
            for (int mt = 0; mt < 4; mt++) {
                int mr = wm * 64 + mt * 16;
                unsigned addr = (unsigned)__cvta_generic_to_shared(
                    &As[mr + (lane & 15)][ks + 8 * (lane >> 4)]);
                asm volatile(
                    "ldmatrix.sync.aligned.m8n8.x4.shared.b16 {%0,%1,%2,%3}, [%4];"
                    : "=r"(a[mt][0]), "=r"(a[mt][1]), "=r"(a[mt][2]), "=r"(a[mt][3])
                    : "r"(addr));
            }
            unsigned b[4][2];
#pragma unroll
            for (int nt = 0; nt < 4; nt++) {
                int nc = wn * 32 + nt * 8;
                unsigned addr = (unsigned)__cvta_generic_to_shared(
                    &Bs[ks + (lane & 15)][nc]);
                asm volatile(
                    "ldmatrix.sync.aligned.m8n8.x2.trans.shared.b16 {%0,%1}, [%2];"
                    : "=r"(b[nt][0]), "=r"(b[nt][1])
                    : "r"(addr));
            }
#pragma unroll
            for (int mt = 0; mt < 4; mt++)
#pragma unroll
                for (int nt = 0; nt < 4; nt++) {
                    asm volatile(
                        "mma.sync.aligned.m16n8k16.row.col.f32.f16.f16.f32 "
                        "{%0,%1,%2,%3}, {%4,%5,%6,%7}, {%8,%9}, {%0,%1,%2,%3};\n"
                        : "+f"(c[mt][nt][0]), "+f"(c[mt][nt][1]),
                          "+f"(c[mt][nt][2]), "+f"(c[mt][nt][3])
                        : "r"(a[mt][0]), "r"(a[mt][1]), "r"(a[mt][2]), "r"(a[mt][3]),
                          "r"(b[nt][0]), "r"(b[nt][1]));
                }
        }
        __syncthreads();
    }

    float psr[8], pdr[8];
#pragma unroll
    for (int ri = 0; ri < 8; ri++) { psr[ri] = 0.f; pdr[ri] = 0.f; }

#pragma unroll
    for (int mt = 0; mt < 4; mt++) {
#pragma unroll
        for (int nt = 0; nt < 4; nt++) {
            int colg = col0 + wn * 32 + nt * 8 + t * 2;
            float a_s0 = att_s[colg], a_s1 = att_s[colg + 1];
            float a_d0 = att_d[colg], a_d1 = att_d[colg + 1];
            psr[mt*2+0] += c[mt][nt][0] * a_s0 + c[mt][nt][1] * a_s1;
            pdr[mt*2+0] += c[mt][nt][0] * a_d0 + c[mt][nt][1] * a_d1;
            psr[mt*2+1] += c[mt][nt][2] * a_s0 + c[mt][nt][3] * a_s1;
            pdr[mt*2+1] += c[mt][nt][2] * a_d0 + c[mt][nt][3] * a_d1;

            int row = row0 + wm * 64 + mt * 16 + g;
            if (row < M)
                *(__half2*)&g_xw1h[row * F1 + colg] =
                    __floats2half2_rn(c[mt][nt][0], c[mt][nt][1]);
            if (row + 8 < M)
                *(__half2*)&g_xw1h[(row + 8) * F1 + colg] =
                    __floats2half2_rn(c[mt][nt][2], c[mt][nt][3]);
        }
    }
#pragma unroll
    for (int ri = 0; ri < 8; ri++) {
        psr[ri] += __shfl_xor_sync(0xffffffffu, psr[ri], 1);
        psr[ri] += __shfl_xor_sync(0xffffffffu, psr[ri], 2);
        pdr[ri] += __shfl_xor_sync(0xffffffffu, pdr[ri], 1);
        pdr[ri] += __shfl_xor_sync(0xffffffffu, pdr[ri], 2);
    }
    if (t == 0) {
#pragma unroll
        for (int ri = 0; ri < 8; ri++) {
            int row = wm * 64 + (ri >> 1) * 16 + g + (ri & 1) * 8;
            ps_s[row][wn] = psr[ri];
            pd_s[row][wn] = pdr[ri];
        }
    }
    __syncthreads();
    if (tid < 128) {
        int node = row0 + tid;
        if (node < M) {
            int hb = blockIdx.x * 2;
            g_a1s[node * H1 + hb    ] = ps_s[tid][0] + ps_s[tid][1];
            g_a1s[node * H1 + hb + 1] = ps_s[tid][2] + ps_s[tid][3];
            g_a1d[node * H1 + hb    ] = pd_s[tid][0] + pd_s[tid][1];
            g_a1d[node * H1 + hb + 1] = pd_s[tid][2] + pd_s[tid][3];
        }
    }
}

// ---------------- sw1e: fill buckets (src + layer1 weights); no atomics ----------------
__global__ void sw1e_kernel(const int* __restrict__ ei, int e, int n) {
    int i = blockIdx.x * blockDim.x + threadIdx.x;
    if (i < e) {
        int d = ei[e + i];
        int s = ei[i];
        int rank = g_epos[i];
        if (d >= 0 && d < n && s >= 0 && s < n && rank >= 0 && rank < EK) {
            int p = d * EK + rank;
            g_srcs[p] = s;
            g_epos[i] = p;
            float4 as = *(const float4*)&g_a1s[s * H1];
            float4 ad = *(const float4*)&g_a1d[d * H1];
            float w0 = __expf(leaky(as.x + ad.x));
            float w1 = __expf(leaky(as.y + ad.y));
            float w2 = __expf(leaky(as.z + ad.z));
            float w3 = __expf(leaky(as.w + ad.w));
            __half2 h0 = __floats2half2_rn(w0, w1);
            __half2 h1 = __floats2half2_rn(w2, w3);
            uint2 packed;
            packed.x = *(unsigned*)&h0;
            packed.y = *(unsigned*)&h1;
            g_w1e[p] = packed;
        } else {
            g_epos[i] = -1;
        }
    }
}

// ---------------- agg1: 1 warp/node, 8 feats/lane; scalar weight load ----------------
__global__ void agg1_kernel(const float* __restrict__ bias1, int n) {
    int node = (blockIdx.x * blockDim.x + threadIdx.x) >> 5;
    int lane = threadIdx.x & 31;
    if (node >= n) return;

    int fb = lane * 8;                 // 8 contiguous halves per lane
    int head = lane >> 3;
    float adh = g_a1d[node * H1 + head];
    float ash = g_a1s[node * H1 + head];

    int start = node * EK;
    int deg   = g_cnt[node];
    deg = deg < EK ? deg : EK;

    const __half* w1e_h = (const __half*)g_w1e;   // scalar view: slot*4 + head

    float w = __expf(leaky(ash + adh));   // self loop
    float sumw = w;
    float acc[8];
    {
        uint4 u = *(const uint4*)&g_xw1h[node * F1 + fb];
        float2 f0 = __half22float2(*(__half2*)&u.x);
        float2 f1 = __half22float2(*(__half2*)&u.y);
        float2 f2 = __half22float2(*(__half2*)&u.z);
        float2 f3 = __half22float2(*(__half2*)&u.w);
        acc[0] = w * f0.x; acc[1] = w * f0.y; acc[2] = w * f1.x; acc[3] = w * f1.y;
        acc[4] = w * f2.x; acc[5] = w * f2.y; acc[6] = w * f3.x; acc[7] = w * f3.y;
    }
#pragma unroll 4
    for (int j = 0; j < deg; j++) {
        int slot = start + j;
        int s = g_srcs[slot];
        float wj = __half2float(w1e_h[slot * 4 + head]);
        sumw += wj;
        uint4 u = *(const uint4*)&g_xw1h[s * F1 + fb];
        float2 f0 = __half22float2(*(__half2*)&u.x);
        float2 f1 = __half22float2(*(__half2*)&u.y);
        float2 f2 = __half22float2(*(__half2*)&u.z);
        float2 f3 = __half22float2(*(__half2*)&u.w);
        acc[0] += wj * f0.x; acc[1] += wj * f0.y; acc[2] += wj * f1.x; acc[3] += wj * f1.y;
        acc[4] += wj * f2.x; acc[5] += wj * f2.y; acc[6] += wj * f3.x; acc[7] += wj * f3.y;
    }
    float inv = 1.f / sumw;
    float o[8];
#pragma unroll
    for (int q = 0; q < 8; q++) {
        float v = acc[q] * inv + bias1[fb + q];
        o[q] = v > 0.f ? v : expm1f(v);   // ELU
    }
    __half2* xp = (__half2*)&g_x2h[node * F1 + fb];
    xp[0] = __floats2half2_rn(o[0], o[1]);
    xp[1] = __floats2half2_rn(o[2], o[3]);
    xp[2] = __floats2half2_rn(o[4], o[5]);
    xp[3] = __floats2half2_rn(o[6], o[7]);
}

// ---------------- GEMM2 + fused att2: 256 rows/block ----------------
#define G2_ROWS 256
__global__ void __launch_bounds__(256) gemm2_kernel(
        const float* __restrict__ W2,
        const float* __restrict__ as2, const float* __restrict__ ad2, int n) {
    __shared__ float Xs[G2_ROWS][17];
    __shared__ float ps_sm[G2_ROWS][4];
    __shared__ float pd_sm[G2_ROWS][4];
    const int tid = threadIdx.x;
    const int rowblk = blockIdx.x * G2_ROWS;
    const int rbase = tid & 63;
    const int cg = tid >> 6;
    const int c0 = cg * 4;

    float acc[4][4];
#pragma unroll
    for (int i = 0; i < 4; i++)
#pragma unroll
        for (int j = 0; j < 4; j++) acc[i][j] = 0.f;

    for (int kb = 0; kb < F1; kb += 16) {
#pragma unroll
        for (int i = 0; i < 4; i++) {
            int lr = (tid >> 2) + 64 * i;
            int gr = rowblk + lr;
            int kc = (tid & 3) * 4;
            float2 fa = make_float2(0.f, 0.f), fb = make_float2(0.f, 0.f);
            if (gr < n) {
                uint2 v = *(const uint2*)&g_x2h[gr * F1 + kb + kc];
                fa = __half22float2(*(__half2*)&v.x);
                fb = __half22float2(*(__half2*)&v.y);
            }
            Xs[lr][kc + 0] = fa.x;
            Xs[lr][kc + 1] = fa.y;
            Xs[lr][kc + 2] = fb.x;
            Xs[lr][kc + 3] = fb.y;
        }
        float4 wr[16];
#pragma unroll
        for (int k = 0; k < 16; k++)
            wr[k] = *(const float4*)&W2[(kb + k) * NCLS + c0];
        __syncthreads();
#pragma unroll
        for (int k = 0; k < 16; k++) {
#pragma unroll
            for (int i = 0; i < 4; i++) {
                float xv = Xs[rbase + 64 * i][k];
                acc[i][0] += xv * wr[k].x;
                acc[i][1] += xv * wr[k].y;
                acc[i][2] += xv * wr[k].z;
                acc[i][3] += xv * wr[k].w;
            }
        }
        __syncthreads();
    }
    // store xw2 + partial att2 dots
    float4 sv = *(const float4*)&as2[c0];
    float4 dv = *(const float4*)&ad2[c0];
#pragma unroll
    for (int i = 0; i < 4; i++) {
        int lr = rbase + 64 * i;
        int gr = rowblk + lr;
        if (gr < n)
            *(float4*)&g_xw2[gr * NCLS + c0] =
                make_float4(acc[i][0], acc[i][1], acc[i][2], acc[i][3]);
        ps_sm[lr][cg] = acc[i][0]*sv.x + acc[i][1]*sv.y + acc[i][2]*sv.z + acc[i][3]*sv.w;
        pd_sm[lr][cg] = acc[i][0]*dv.x + acc[i][1]*dv.y + acc[i][2]*dv.z + acc[i][3]*dv.w;
    }
    __syncthreads();
    {
        int gr = rowblk + tid;
        if (tid < G2_ROWS && gr < n) {
            g_a2s[gr] = ps_sm[tid][0] + ps_sm[tid][1] + ps_sm[tid][2] + ps_sm[tid][3];
            g_a2d[gr] = pd_sm[tid][0] + pd_sm[tid][1] + pd_sm[tid][2] + pd_sm[tid][3];
        }
    }
}

// ---------------- w2e: layer2 edge weights (edge-parallel) ----------------
__global__ void w2e_kernel(const int* __restrict__ ei, int e, int n) {
    int i = blockIdx.x * blockDim.x + threadIdx.x;
    if (i < e) {
        int p = g_epos[i];
        if (p >= 0 && p < MAXN * EK) {
            int d = ei[e + i];
            int s = ei[i];
            g_w2e[p] = __expf(leaky(g_a2s[s] + g_a2d[d]));
        }
    }
}

// ---------------- agg2 + final softmax + g_cnt re-zero for next run ----------------
__global__ void agg2_kernel(const float* __restrict__ bias2,
                            float* __restrict__ out, int n) {
    int node = (blockIdx.x * blockDim.x + threadIdx.x) >> 5;
    int lane = threadIdx.x & 31;
    if (node >= n) return;

    int half_ = lane >> 4;
    int c     = lane & 15;
    float sumw = 0.f, acc = 0.f;
    if (half_ == 0) {
        float w = __expf(leaky(g_a2s[node] + g_a2d[node]));
        sumw = w;
        acc  = w * g_xw2[node * NCLS + c];
    }
    int start = node * EK;
    int deg   = g_cnt[node];
    deg = deg < EK ? deg : EK;
#pragma unroll 4
    for (int j = half_; j < deg; j += 2) {
        int s = g_srcs[start + j];
        float wj = g_w2e[start + j];
        sumw += wj;
        acc  += wj * g_xw2[s * NCLS + c];
    }
    sumw += __shfl_xor_sync(0xffffffffu, sumw, 16);
    acc  += __shfl_xor_sync(0xffffffffu, acc, 16);

    float logit = acc / sumw + bias2[c];

    float mx = logit;
#pragma unroll
    for (int off = 8; off > 0; off >>= 1)
        mx = fmaxf(mx, __shfl_xor_sync(0xffffffffu, mx, off));
    float p = __expf(logit - mx);
    float s16 = p;
#pragma unroll
    for (int off = 8; off > 0; off >>= 1)
        s16 += __shfl_xor_sync(0xffffffffu, s16, off);
    if (lane < NCLS) out[node * NCLS + lane] = p / s16;

    // re-zero this node's degree for the next run (deg already read above)
    if (lane == 0) g_cnt[node] = 0;
}

// ---------------- launch ----------------
extern "C" void kernel_launch(void* const* d_in, const int* in_sizes, int n_in,
                              void* d_out, int out_size) {
    const float* obs  = (const float*)d_in[0];
    const int*   ei   = (const int*)d_in[1];   // int32 (confirmed: int64 read crashes)
    const float* W1   = (const float*)d_in[2];
    const float* as1  = (const float*)d_in[3];
    const float* ad1  = (const float*)d_in[4];
    const float* b1   = (const float*)d_in[5];
    const float* W2   = (const float*)d_in[6];
    const float* as2  = (const float*)d_in[7];
    const float* ad2  = (const float*)d_in[8];
    const float* b2   = (const float*)d_in[9];
    float* out = (float*)d_out;

    int n = in_sizes[0] / NFEAT;
    int e = in_sizes[1] / 2;
    int m4 = n * NFEAT / 4;
    int prep_threads = m4 > e ? m4 : e;

    prep_kernel<<<(prep_threads + 255) / 256, 256>>>(obs, W1, ei, e, n, m4); // 0
    gemm1_mma_kernel<<<dim3(F1 / 128, (n + 127) / 128), 256>>>(as1, ad1, n); // 1
    sw1e_kernel<<<(e + 255) / 256, 256>>>(ei, e, n);                         // 2
    agg1_kernel<<<(n + 7) / 8, 256>>>(b1, n);                                // 3 (ncu slot)
    gemm2_kernel<<<(n + G2_ROWS - 1) / G2_ROWS, 256>>>(W2, as2, ad2, n);     // 4
    w2e_kernel<<<(e + 255) / 256, 256>>>(ei, e, n);                          // 5
    agg2_kernel<<<(n + 7) / 8, 256>>>(b2, out, n);                           // 6
}

// round 13
// speedup vs baseline: 1.7494x; 1.0323x over previous
#include <cuda_runtime.h>
#include <cuda_fp16.h>
#include <math.h>

// Problem constants (fixed by the dataset)
#define NFEAT 128
#define F1    256      // H1*NHID
#define H1    4
#define NHID  64
#define NCLS  16
#define MAXN  50048
#define MAXE  800000
#define EK    96       // fixed bucket stride (max in-degree; Poisson(16) => P(>=96) ~ 1e-40)

#define NEG_SLOPE 0.2f

// ---------------- scratch (static __device__, no allocation) ----------------
__device__ __align__(16) __half g_obsh[MAXN * NFEAT];  // obs fp16 (tail rows stay 0)
__device__ __align__(16) __half g_w1h [NFEAT * F1];    // W1 fp16
__device__ __align__(16) __half g_xw1h[MAXN * F1];     // layer1 x@W1 (fp16)
__device__ __align__(16) __half g_x2h [MAXN * F1];     // layer1 output after ELU (fp16)
__device__ __align__(16) float g_a1s[MAXN * H1];
__device__ __align__(16) float g_a1d[MAXN * H1];
__device__ __align__(16) float g_xw2[MAXN * NCLS];
__device__ float g_a2s[MAXN];
__device__ float g_a2d[MAXN];
__device__ int   g_cnt[MAXN];                  // ZERO at entry (BSS + agg2 re-zeroes)
__device__ int   g_srcs[MAXN * EK];            // src ids, fixed-stride buckets
__device__ int   g_epos[MAXE];                 // prep: rank; sw1e: final slot (or -1)
__device__ __align__(8) uint2 g_w1e[MAXN * EK];// layer1 edge weights, fp16 x4 heads
__device__ float g_w2e[MAXN * EK];             // layer2 edge weights

__device__ __forceinline__ float leaky(float x) {
    return x > 0.f ? x : NEG_SLOPE * x;
}

// ---------------- prep: conversions + histogram with rank capture ----------------
__global__ void prep_kernel(const float* __restrict__ obs,
                            const float* __restrict__ W1,
                            const int* __restrict__ ei, int e, int n, int m4) {
    int i = blockIdx.x * blockDim.x + threadIdx.x;
    if (i < m4) {
        float4 v = *(const float4*)&obs[i * 4];
        __half2* dst = (__half2*)&g_obsh[i * 4];
        dst[0] = __floats2half2_rn(v.x, v.y);
        dst[1] = __floats2half2_rn(v.z, v.w);
    }
    if (i < NFEAT * F1 / 4) {
        float4 v = *(const float4*)&W1[i * 4];
        __half2* dst = (__half2*)&g_w1h[i * 4];
        dst[0] = __floats2half2_rn(v.x, v.y);
        dst[1] = __floats2half2_rn(v.z, v.w);
    }
    if (i < e) {                       // histogram; atomic return value = rank in bucket
        int d = ei[e + i];
        if (d >= 0 && d < n) {
            g_epos[i] = atomicAdd(&g_cnt[d], 1);
        } else {
            g_epos[i] = -1;
        }
    }
}

// ---------------- GEMM1 (HMMA + ldmatrix) + fused att1 ----------------
__global__ void __launch_bounds__(256, 2) gemm1_mma_kernel(
        const float* __restrict__ att_s, const float* __restrict__ att_d, int M) {
    __shared__ __half As[128][72];
    __shared__ __half Bs[64][136];
    __shared__ float ps_s[128][4];
    __shared__ float pd_s[128][4];
    const int tid  = threadIdx.x;
    const int wid  = tid >> 5;
    const int lane = tid & 31;
    const int wm = wid >> 2;
    const int wn = wid & 3;
    const int g  = lane >> 2;
    const int t  = lane & 3;
    const int row0 = blockIdx.y * 128;
    const int col0 = blockIdx.x * 128;

    float c[4][4][4];
#pragma unroll
    for (int mt = 0; mt < 4; mt++)
#pragma unroll
        for (int nt = 0; nt < 4; nt++)
#pragma unroll
            for (int q = 0; q < 4; q++) c[mt][nt][q] = 0.f;

    for (int kb = 0; kb < NFEAT; kb += 64) {
#pragma unroll
        for (int i = 0; i < 8; i++) {
            int idx = tid + i * 256;
            int r = idx >> 4;
            int q = idx & 15;
            *(uint2*)&As[r][q * 4] =
                *(const uint2*)&g_obsh[(row0 + r) * NFEAT + kb + q * 4];
        }
#pragma unroll
        for (int i = 0; i < 8; i++) {
            int idx = tid + i * 256;
            int kr = idx >> 5;
            int nq = idx & 31;
            *(uint2*)&Bs[kr][nq * 4] =
                *(const uint2*)&g_w1h[(kb + kr) * F1 + col0 + nq * 4];
        }
        __syncthreads();
#pragma unroll
        for (int ks = 0; ks < 64; ks += 16) {
            unsigned a[4][4];
#pragma unroll
            for (int mt = 0; mt < 4; mt++) {
                int mr = wm * 64 + mt * 16;
                unsigned addr = (unsigned)__cvta_generic_to_shared(
                    &As[mr + (lane & 15)][ks + 8 * (lane >> 4)]);
                asm volatile(
                    "ldmatrix.sync.aligned.m8n8.x4.shared.b16 {%0,%1,%2,%3}, [%4];"
                    : "=r"(a[mt][0]), "=r"(a[mt][1]), "=r"(a[mt][2]), "=r"(a[mt][3])
                    : "r"(addr));
            }
            unsigned b[4][2];
#pragma unroll
            for (int nt = 0; nt < 4; nt++) {
                int nc = wn * 32 + nt * 8;
                unsigned addr = (unsigned)__cvta_generic_to_shared(
                    &Bs[ks + (lane & 15)][nc]);
                asm volatile(
                    "ldmatrix.sync.aligned.m8n8.x2.trans.shared.b16 {%0,%1}, [%2];"
                    : "=r"(b[nt][0]), "=r"(b[nt][1])
                    : "r"(addr));
            }
#pragma unroll
            for (int mt = 0; mt < 4; mt++)
#pragma unroll
                for (int nt = 0; nt < 4; nt++) {
                    asm volatile(
                        "mma.sync.aligned.m16n8k16.row.col.f32.f16.f16.f32 "
                        "{%0,%1,%2,%3}, {%4,%5,%6,%7}, {%8,%9}, {%0,%1,%2,%3};\n"
                        : "+f"(c[mt][nt][0]), "+f"(c[mt][nt][1]),
                          "+f"(c[mt][nt][2]), "+f"(c[mt][nt][3])
                        : "r"(a[mt][0]), "r"(a[mt][1]), "r"(a[mt][2]), "r"(a[mt][3]),
                          "r"(b[nt][0]), "r"(b[nt][1]));
                }
        }
        __syncthreads();
    }

    float psr[8], pdr[8];
#pragma unroll
    for (int ri = 0; ri < 8; ri++) { psr[ri] = 0.f; pdr[ri] = 0.f; }

#pragma unroll
    for (int mt = 0; mt < 4; mt++) {
#pragma unroll
        for (int nt = 0; nt < 4; nt++) {
            int colg = col0 + wn * 32 + nt * 8 + t * 2;
            float a_s0 = att_s[colg], a_s1 = att_s[colg + 1];
            float a_d0 = att_d[colg], a_d1 = att_d[colg + 1];
            psr[mt*2+0] += c[mt][nt][0] * a_s0 + c[mt][nt][1] * a_s1;
            pdr[mt*2+0] += c[mt][nt][0] * a_d0 + c[mt][nt][1] * a_d1;
            psr[mt*2+1] += c[mt][nt][2] * a_s0 + c[mt][nt][3] * a_s1;
            pdr[mt*2+1] += c[mt][nt][2] * a_d0 + c[mt][nt][3] * a_d1;

            int row = row0 + wm * 64 + mt * 16 + g;
            if (row < M)
                *(__half2*)&g_xw1h[row * F1 + colg] =
                    __floats2half2_rn(c[mt][nt][0], c[mt][nt][1]);
            if (row + 8 < M)
                *(__half2*)&g_xw1h[(row + 8) * F1 + colg] =
                    __floats2half2_rn(c[mt][nt][2], c[mt][nt][3]);
        }
    }
#pragma unroll
    for (int ri = 0; ri < 8; ri++) {
        psr[ri] += __shfl_xor_sync(0xffffffffu, psr[ri], 1);
        psr[ri] += __shfl_xor_sync(0xffffffffu, psr[ri], 2);
        pdr[ri] += __shfl_xor_sync(0xffffffffu, pdr[ri], 1);
        pdr[ri] += __shfl_xor_sync(0xffffffffu, pdr[ri], 2);
    }
    if (t == 0) {
#pragma unroll
        for (int ri = 0; ri < 8; ri++) {
            int row = wm * 64 + (ri >> 1) * 16 + g + (ri & 1) * 8;
            ps_s[row][wn] = psr[ri];
            pd_s[row][wn] = pdr[ri];
        }
    }
    __syncthreads();
    if (tid < 128) {
        int node = row0 + tid;
        if (node < M) {
            int hb = blockIdx.x * 2;
            g_a1s[node * H1 + hb    ] = ps_s[tid][0] + ps_s[tid][1];
            g_a1s[node * H1 + hb + 1] = ps_s[tid][2] + ps_s[tid][3];
            g_a1d[node * H1 + hb    ] = pd_s[tid][0] + pd_s[tid][1];
            g_a1d[node * H1 + hb + 1] = pd_s[tid][2] + pd_s[tid][3];
        }
    }
}

// ---------------- sw1e: fill buckets (src + layer1 weights); no atomics ----------------
__global__ void sw1e_kernel(const int* __restrict__ ei, int e, int n) {
    int i = blockIdx.x * blockDim.x + threadIdx.x;
    if (i < e) {
        int d = ei[e + i];
        int s = ei[i];
        int rank = g_epos[i];
        if (d >= 0 && d < n && s >= 0 && s < n && rank >= 0 && rank < EK) {
            int p = d * EK + rank;
            g_srcs[p] = s;
            g_epos[i] = p;
            float4 as = *(const float4*)&g_a1s[s * H1];
            float4 ad = *(const float4*)&g_a1d[d * H1];
            float w0 = __expf(leaky(as.x + ad.x));
            float w1 = __expf(leaky(as.y + ad.y));
            float w2 = __expf(leaky(as.z + ad.z));
            float w3 = __expf(leaky(as.w + ad.w));
            __half2 h0 = __floats2half2_rn(w0, w1);
            __half2 h1 = __floats2half2_rn(w2, w3);
            uint2 packed;
            packed.x = *(unsigned*)&h0;
            packed.y = *(unsigned*)&h1;
            g_w1e[p] = packed;
        } else {
            g_epos[i] = -1;
        }
    }
}

// ---------------- agg1: 1 warp/node, 8 feats/lane; HFMA2 accumulation ----------------
__global__ void agg1_kernel(const float* __restrict__ bias1, int n) {
    int node = (blockIdx.x * blockDim.x + threadIdx.x) >> 5;
    int lane = threadIdx.x & 31;
    if (node >= n) return;

    int fb = lane * 8;                 // 8 contiguous halves per lane
    int head = lane >> 3;
    float adh = g_a1d[node * H1 + head];
    float ash = g_a1s[node * H1 + head];

    int start = node * EK;
    int deg   = g_cnt[node];
    deg = deg < EK ? deg : EK;

    const __half* w1e_h = (const __half*)g_w1e;   // scalar view: slot*4 + head

    float w = __expf(leaky(ash + adh));   // self loop (fp32)
    float sumw = w;
    __half2 acc2[4];
    {
        __half2 wh = __float2half2_rn(w);
        uint4 u = *(const uint4*)&g_xw1h[node * F1 + fb];
        acc2[0] = __hmul2(wh, *(__half2*)&u.x);
        acc2[1] = __hmul2(wh, *(__half2*)&u.y);
        acc2[2] = __hmul2(wh, *(__half2*)&u.z);
        acc2[3] = __hmul2(wh, *(__half2*)&u.w);
    }
#pragma unroll 4
    for (int j = 0; j < deg; j++) {
        int slot = start + j;
        int s = g_srcs[slot];
        __half whj = w1e_h[slot * 4 + head];
        sumw += __half2float(whj);            // sumw stays fp32
        __half2 wj2 = __half2half2(whj);
        uint4 u = *(const uint4*)&g_xw1h[s * F1 + fb];
        acc2[0] = __hfma2(wj2, *(__half2*)&u.x, acc2[0]);
        acc2[1] = __hfma2(wj2, *(__half2*)&u.y, acc2[1]);
        acc2[2] = __hfma2(wj2, *(__half2*)&u.z, acc2[2]);
        acc2[3] = __hfma2(wj2, *(__half2*)&u.w, acc2[3]);
    }
    float inv = 1.f / sumw;
    float2 f0 = __half22float2(acc2[0]);
    float2 f1 = __half22float2(acc2[1]);
    float2 f2 = __half22float2(acc2[2]);
    float2 f3 = __half22float2(acc2[3]);
    float av[8] = {f0.x, f0.y, f1.x, f1.y, f2.x, f2.y, f3.x, f3.y};
    float o[8];
#pragma unroll
    for (int q = 0; q < 8; q++) {
        float v = av[q] * inv + bias1[fb + q];
        o[q] = v > 0.f ? v : expm1f(v);   // ELU
    }
    __half2* xp = (__half2*)&g_x2h[node * F1 + fb];
    xp[0] = __floats2half2_rn(o[0], o[1]);
    xp[1] = __floats2half2_rn(o[2], o[3]);
    xp[2] = __floats2half2_rn(o[4], o[5]);
    xp[3] = __floats2half2_rn(o[6], o[7]);
}

// ---------------- GEMM2 + fused att2: 256 rows/block ----------------
#define G2_ROWS 256
__global__ void __launch_bounds__(256) gemm2_kernel(
        const float* __restrict__ W2,
        const float* __restrict__ as2, const float* __restrict__ ad2, int n) {
    __shared__ float Xs[G2_ROWS][17];
    __shared__ float ps_sm[G2_ROWS][4];
    __shared__ float pd_sm[G2_ROWS][4];
    const int tid = threadIdx.x;
    const int rowblk = blockIdx.x * G2_ROWS;
    const int rbase = tid & 63;
    const int cg = tid >> 6;
    const int c0 = cg * 4;

    float acc[4][4];
#pragma unroll
    for (int i = 0; i < 4; i++)
#pragma unroll
        for (int j = 0; j < 4; j++) acc[i][j] = 0.f;

    for (int kb = 0; kb < F1; kb += 16) {
#pragma unroll
        for (int i = 0; i < 4; i++) {
            int lr = (tid >> 2) + 64 * i;
            int gr = rowblk + lr;
            int kc = (tid & 3) * 4;
            float2 fa = make_float2(0.f, 0.f), fb = make_float2(0.f, 0.f);
            if (gr < n) {
                uint2 v = *(const uint2*)&g_x2h[gr * F1 + kb + kc];
                fa = __half22float2(*(__half2*)&v.x);
                fb = __half22float2(*(__half2*)&v.y);
            }
            Xs[lr][kc + 0] = fa.x;
            Xs[lr][kc + 1] = fa.y;
            Xs[lr][kc + 2] = fb.x;
            Xs[lr][kc + 3] = fb.y;
        }
        float4 wr[16];
#pragma unroll
        for (int k = 0; k < 16; k++)
            wr[k] = *(const float4*)&W2[(kb + k) * NCLS + c0];
        __syncthreads();
#pragma unroll
        for (int k = 0; k < 16; k++) {
#pragma unroll
            for (int i = 0; i < 4; i++) {
                float xv = Xs[rbase + 64 * i][k];
                acc[i][0] += xv * wr[k].x;
                acc[i][1] += xv * wr[k].y;
                acc[i][2] += xv * wr[k].z;
                acc[i][3] += xv * wr[k].w;
            }
        }
        __syncthreads();
    }
    // store xw2 + partial att2 dots
    float4 sv = *(const float4*)&as2[c0];
    float4 dv = *(const float4*)&ad2[c0];
#pragma unroll
    for (int i = 0; i < 4; i++) {
        int lr = rbase + 64 * i;
        int gr = rowblk + lr;
        if (gr < n)
            *(float4*)&g_xw2[gr * NCLS + c0] =
                make_float4(acc[i][0], acc[i][1], acc[i][2], acc[i][3]);
        ps_sm[lr][cg] = acc[i][0]*sv.x + acc[i][1]*sv.y + acc[i][2]*sv.z + acc[i][3]*sv.w;
        pd_sm[lr][cg] = acc[i][0]*dv.x + acc[i][1]*dv.y + acc[i][2]*dv.z + acc[i][3]*dv.w;
    }
    __syncthreads();
    {
        int gr = rowblk + tid;
        if (tid < G2_ROWS && gr < n) {
            g_a2s[gr] = ps_sm[tid][0] + ps_sm[tid][1] + ps_sm[tid][2] + ps_sm[tid][3];
            g_a2d[gr] = pd_sm[tid][0] + pd_sm[tid][1] + pd_sm[tid][2] + pd_sm[tid][3];
        }
    }
}

// ---------------- w2e: layer2 edge weights (edge-parallel) ----------------
__global__ void w2e_kernel(const int* __restrict__ ei, int e, int n) {
    int i = blockIdx.x * blockDim.x + threadIdx.x;
    if (i < e) {
        int p = g_epos[i];
        if (p >= 0 && p < MAXN * EK) {
            int d = ei[e + i];
            int s = ei[i];
            g_w2e[p] = __expf(leaky(g_a2s[s] + g_a2d[d]));
        }
    }
}

// ---------------- agg2 + final softmax + g_cnt re-zero for next run ----------------
__global__ void agg2_kernel(const float* __restrict__ bias2,
                            float* __restrict__ out, int n) {
    int node = (blockIdx.x * blockDim.x + threadIdx.x) >> 5;
    int lane = threadIdx.x & 31;
    if (node >= n) return;

    int half_ = lane >> 4;
    int c     = lane & 15;
    float sumw = 0.f, acc = 0.f;
    if (half_ == 0) {
        float w = __expf(leaky(g_a2s[node] + g_a2d[node]));
        sumw = w;
        acc  = w * g_xw2[node * NCLS + c];
    }
    int start = node * EK;
    int deg   = g_cnt[node];
    deg = deg < EK ? deg : EK;
#pragma unroll 4
    for (int j = half_; j < deg; j += 2) {
        int s = g_srcs[start + j];
        float wj = g_w2e[start + j];
        sumw += wj;
        acc  += wj * g_xw2[s * NCLS + c];
    }
    sumw += __shfl_xor_sync(0xffffffffu, sumw, 16);
    acc  += __shfl_xor_sync(0xffffffffu, acc, 16);

    float logit = acc / sumw + bias2[c];

    float mx = logit;
#pragma unroll
    for (int off = 8; off > 0; off >>= 1)
        mx = fmaxf(mx, __shfl_xor_sync(0xffffffffu, mx, off));
    float p = __expf(logit - mx);
    float s16 = p;
#pragma unroll
    for (int off = 8; off > 0; off >>= 1)
        s16 += __shfl_xor_sync(0xffffffffu, s16, off);
    if (lane < NCLS) out[node * NCLS + lane] = p / s16;

    // re-zero this node's degree for the next run (deg already read above)
    if (lane == 0) g_cnt[node] = 0;
}

// ---------------- launch ----------------
extern "C" void kernel_launch(void* const* d_in, const int* in_sizes, int n_in,
                              void* d_out, int out_size) {
    const float* obs  = (const float*)d_in[0];
    const int*   ei   = (const int*)d_in[1];   // int32 (confirmed: int64 read crashes)
    const float* W1   = (const float*)d_in[2];
    const float* as1  = (const float*)d_in[3];
    const float* ad1  = (const float*)d_in[4];
    const float* b1   = (const float*)d_in[5];
    const float* W2   = (const float*)d_in[6];
    const float* as2  = (const float*)d_in[7];
    const float* ad2  = (const float*)d_in[8];
    const float* b2   = (const float*)d_in[9];
    float* out = (float*)d_out;

    int n = in_sizes[0] / NFEAT;
    int e = in_sizes[1] / 2;
    int m4 = n * NFEAT / 4;
    int prep_threads = m4 > e ? m4 : e;

    prep_kernel<<<(prep_threads + 255) / 256, 256>>>(obs, W1, ei, e, n, m4); // 0
    gemm1_mma_kernel<<<dim3(F1 / 128, (n + 127) / 128), 256>>>(as1, ad1, n); // 1
    sw1e_kernel<<<(e + 255) / 256, 256>>>(ei, e, n);                         // 2
    agg1_kernel<<<(n + 7) / 8, 256>>>(b1, n);                                // 3 (ncu slot)
    gemm2_kernel<<<(n + G2_ROWS - 1) / G2_ROWS, 256>>>(W2, as2, ad2, n);     // 4
    w2e_kernel<<<(e + 255) / 256, 256>>>(ei, e, n);                          // 5
    agg2_kernel<<<(n + 7) / 8, 256>>>(b2, out, n);                           // 6
}